// round 13
// baseline (speedup 1.0000x reference)
#include <cuda_runtime.h>
#include <cuda_bf16.h>
#include <math.h>
#include <float.h>
#include <stdint.h>

#define NN   8192
#define FIN  256
#define HIDD 256
#define NE   131072
#define KT   17
#define CANDCAP 96
#define NCLS 10
#define NSEL 4096
#define EPSF 1e-8f

__device__ __align__(16) float d_fea[NN * FIN];
__device__ __align__(16) __nv_bfloat16 d_feah[NN * FIN];
__device__ __align__(16) __nv_bfloat16 d_feal[NN * FIN];
__device__ float d_dinv[NN];
__device__ int   d_cnt_e[NN];          // self-clean in k_scan
__device__ int   d_rptr[NN + 1];
__device__ int   d_cur[NN];
__device__ int   d_csrc[NE];
__device__ float d_cw[NE];
__device__ __align__(16) float d_hn[NN * 512];
__device__ __align__(16) __nv_bfloat16 d_hb[NN * 512];
__device__ __nv_bfloat16 d_simh[(size_t)NN * NN];
__device__ int   d_tidx[NN * KT];
__device__ float d_tval[NN * KT];
__device__ int   d_kcnt[NN];           // self-clean in k_kscan
__device__ int   d_kptr[NN + 1];
__device__ int   d_kcur[NN];
__device__ unsigned char d_kmut[NN * KT];
__device__ int   d_kidx[NN * KT * 2];
__device__ float d_kval[NN * KT * 2];
__device__ __align__(16) __nv_bfloat16 d_w1h[FIN * HIDD];
__device__ __align__(16) __nv_bfloat16 d_w1l[FIN * HIDD];
__device__ __align__(16) __nv_bfloat16 d_w2h[HIDD * HIDD];
__device__ __align__(16) __nv_bfloat16 d_w2l[HIDD * HIDD];
__device__ __align__(16) float d_xw[NN * HIDD];
__device__ __align__(16) float d_h1[NN * HIDD];
__device__ __align__(16) __nv_bfloat16 d_h1h[NN * HIDD];
__device__ __align__(16) __nv_bfloat16 d_h1l[NN * HIDD];
__device__ __align__(16) float d_hw[NN * HIDD];
__device__ __align__(16) float d_emb[NN * HIDD];
__device__ __align__(16) float d_sums[NCLS * HIDD]; // self-clean in k_proto
__device__ float d_cnt[NCLS];                       // self-clean in k_proto
__device__ float d_pn[NCLS * HIDD];

__device__ __forceinline__ float warp_sum(float v) {
#pragma unroll
    for (int o = 16; o > 0; o >>= 1) v += __shfl_xor_sync(0xffffffffu, v, o);
    return v;
}
__device__ __forceinline__ void red4(float4* addr, float a, float b, float c, float d) {
    asm volatile("red.global.add.v4.f32 [%0], {%1,%2,%3,%4};"
                 :: "l"(addr), "f"(a), "f"(b), "f"(c), "f"(d) : "memory");
}
__device__ __forceinline__ void fma4(float4& a, float w, const float4 v) {
    a.x += w * v.x; a.y += w * v.y; a.z += w * v.z; a.w += w * v.w;
}
__device__ __forceinline__ uint2 pack_bf16x4(float4 v) {
    __nv_bfloat162 lo = __floats2bfloat162_rn(v.x, v.y);
    __nv_bfloat162 hi = __floats2bfloat162_rn(v.z, v.w);
    uint2 r;
    r.x = *reinterpret_cast<uint32_t*>(&lo);
    r.y = *reinterpret_cast<uint32_t*>(&hi);
    return r;
}
__device__ __forceinline__ uint32_t bf16key(uint32_t b) {  // monotone 16-bit key
    return (b & 0x8000u) ? (~b & 0xFFFFu) : (b | 0x8000u);
}

// -------- fea = elu(...) x4 vectorized (full 2M elems) + guarded count/wpack ----
__global__ void k_fea(const float* __restrict__ x, const float* __restrict__ cw,
                      const float* __restrict__ ps, const float* __restrict__ st,
                      const int* __restrict__ dst,
                      const float* __restrict__ W1, const float* __restrict__ W2) {
    int idx = blockIdx.x * 256 + threadIdx.x;       // 0..524287 (= NN*FIN/4)
    int base = idx * 4;
    int f = base & (FIN - 1);
    float c0 = cw[0], c1 = cw[1];
    float4 xv = *(const float4*)&x[base];
    float4 pv = *(const float4*)&ps[f];
    float4 sv = *(const float4*)&st[f];
    float4 r;
    r.x = xv.x * (c0 * pv.x + c1 * sv.x);
    r.y = xv.y * (c0 * pv.y + c1 * sv.y);
    r.z = xv.z * (c0 * pv.z + c1 * sv.z);
    r.w = xv.w * (c0 * pv.w + c1 * sv.w);
    r.x = r.x > 0.f ? r.x : expm1f(r.x);
    r.y = r.y > 0.f ? r.y : expm1f(r.y);
    r.z = r.z > 0.f ? r.z : expm1f(r.z);
    r.w = r.w > 0.f ? r.w : expm1f(r.w);
    *(float4*)&d_fea[base] = r;
    uint2 hp = pack_bf16x4(r);
    *(uint2*)&d_feah[base] = hp;
    __nv_bfloat162* hv = (__nv_bfloat162*)&hp;
    float4 res = make_float4(r.x - __bfloat162float(__low2bfloat16(hv[0])),
                             r.y - __bfloat162float(__high2bfloat16(hv[0])),
                             r.z - __bfloat162float(__low2bfloat16(hv[1])),
                             r.w - __bfloat162float(__high2bfloat16(hv[1])));
    *(uint2*)&d_feal[base] = pack_bf16x4(res);
    if (idx < NE) {
        // one edge per thread
        atomicAdd(&d_cnt_e[dst[idx]], 1);
        // fused weight transpose + split
        int wsel = idx >> 16;
        int e = idx & 0xFFFF;
        int k = e >> 8, n = e & 255;
        float v = (wsel ? W2 : W1)[e];
        __nv_bfloat16 wh = __float2bfloat16(v);
        (wsel ? d_w2h : d_w1h)[n * 256 + k] = wh;
        (wsel ? d_w2l : d_w1l)[n * 256 + k] = __float2bfloat16(v - __bfloat162float(wh));
    }
}
// -------- scan (+self-clean counts) --------
__global__ void k_scan() {
    __shared__ int bs[256];
    int t = threadIdx.x;
    int loc[32]; int s = 0;
#pragma unroll
    for (int q = 0; q < 32; q++) {
        loc[q] = d_cnt_e[t * 32 + q];
        d_cnt_e[t * 32 + q] = 0;
        s += loc[q];
    }
    bs[t] = s; __syncthreads();
    for (int off = 1; off < 256; off <<= 1) {
        int v = (t >= off) ? bs[t - off] : 0;
        __syncthreads();
        bs[t] += v;
        __syncthreads();
    }
    int run = bs[t] - s;
#pragma unroll
    for (int q = 0; q < 32; q++) {
        int i = t * 32 + q;
        d_rptr[i] = run; d_cur[i] = run;
        d_dinv[i] = rsqrtf((float)(loc[q] + 1));
        run += loc[q];
    }
    if (t == 255) d_rptr[NN] = run;
}
__global__ void k_fill(const int* __restrict__ src, const int* __restrict__ dst) {
    int e = blockIdx.x * 256 + threadIdx.x;
    if (e >= NE) return;
    int s = src[e], d = dst[e];
    int pos = atomicAdd(&d_cur[d], 1);
    d_csrc[pos] = s;
    d_cw[pos] = d_dinv[s] * d_dinv[d];
}
// -------- fused aggregate-gather (unroll 4) + h-normalize + bf16 --------
__global__ void k_agg_h(const float* __restrict__ bal) {
    int gw = (blockIdx.x * 256 + threadIdx.x) >> 5, lane = threadIdx.x & 31;
    if (gw >= NN) return;
    float di = d_dinv[gw];
    const float4* fr = (const float4*)(d_fea + (size_t)gw * 256);
    float4 f0 = fr[lane], f1 = fr[lane + 32];
    float sc = di * di;
    float4 a0 = make_float4(sc*f0.x, sc*f0.y, sc*f0.z, sc*f0.w);
    float4 a1 = make_float4(sc*f1.x, sc*f1.y, sc*f1.z, sc*f1.w);
    int b = d_rptr[gw], e = d_rptr[gw + 1];
    int p = b;
    for (; p + 3 < e; p += 4) {
        float w0 = d_cw[p], w1 = d_cw[p+1], w2 = d_cw[p+2], w3 = d_cw[p+3];
        const float4* s0 = (const float4*)(d_fea + (size_t)d_csrc[p] * 256);
        const float4* s1 = (const float4*)(d_fea + (size_t)d_csrc[p+1] * 256);
        const float4* s2 = (const float4*)(d_fea + (size_t)d_csrc[p+2] * 256);
        const float4* s3 = (const float4*)(d_fea + (size_t)d_csrc[p+3] * 256);
        float4 v00 = s0[lane], v01 = s0[lane+32];
        float4 v10 = s1[lane], v11 = s1[lane+32];
        float4 v20 = s2[lane], v21 = s2[lane+32];
        float4 v30 = s3[lane], v31 = s3[lane+32];
        fma4(a0, w0, v00); fma4(a1, w0, v01);
        fma4(a0, w1, v10); fma4(a1, w1, v11);
        fma4(a0, w2, v20); fma4(a1, w2, v21);
        fma4(a0, w3, v30); fma4(a1, w3, v31);
    }
    for (; p < e; p++) {
        float wv = d_cw[p];
        const float4* fs = (const float4*)(d_fea + (size_t)d_csrc[p] * 256);
        fma4(a0, wv, fs[lane]); fma4(a1, wv, fs[lane + 32]);
    }
    const float4* bb = (const float4*)bal;
    float4 bA = bb[lane], bB = bb[lane + 32], bC = bb[64 + lane], bD = bb[96 + lane];
    float4 hA = make_float4(f0.x*bA.x, f0.y*bA.y, f0.z*bA.z, f0.w*bA.w);
    float4 hB = make_float4(f1.x*bB.x, f1.y*bB.y, f1.z*bB.z, f1.w*bB.w);
    float4 hC = make_float4(a0.x*bC.x, a0.y*bC.y, a0.z*bC.z, a0.w*bC.w);
    float4 hD = make_float4(a1.x*bD.x, a1.y*bD.y, a1.z*bD.z, a1.w*bD.w);
    float ss = hA.x*hA.x+hA.y*hA.y+hA.z*hA.z+hA.w*hA.w
             + hB.x*hB.x+hB.y*hB.y+hB.z*hB.z+hB.w*hB.w
             + hC.x*hC.x+hC.y*hC.y+hC.z*hC.z+hC.w*hC.w
             + hD.x*hD.x+hD.y*hD.y+hD.z*hD.z+hD.w*hD.w;
    ss = warp_sum(ss);
    float rn = 1.f / (sqrtf(ss) + EPSF);
    hA.x*=rn; hA.y*=rn; hA.z*=rn; hA.w*=rn;
    hB.x*=rn; hB.y*=rn; hB.z*=rn; hB.w*=rn;
    hC.x*=rn; hC.y*=rn; hC.z*=rn; hC.w*=rn;
    hD.x*=rn; hD.y*=rn; hD.z*=rn; hD.w*=rn;
    float4* hr = (float4*)(d_hn + (size_t)gw * 512);
    hr[lane] = hA; hr[lane + 32] = hB; hr[64 + lane] = hC; hr[96 + lane] = hD;
    uint2* hb = (uint2*)(d_hb + (size_t)gw * 512);
    hb[lane] = pack_bf16x4(hA); hb[lane + 32] = pack_bf16x4(hB);
    hb[64 + lane] = pack_bf16x4(hC); hb[96 + lane] = pack_bf16x4(hD);
}

// ======== mma helpers ========
__device__ __forceinline__ uint32_t smem_u32(const void* p) {
    uint32_t a;
    asm("{ .reg .u64 t; cvta.to.shared.u64 t, %1; cvt.u32.u64 %0, t; }" : "=r"(a) : "l"(p));
    return a;
}
__device__ __forceinline__ void ldsm4(uint32_t* r, uint32_t addr) {
    asm volatile("ldmatrix.sync.aligned.m8n8.x4.shared.b16 {%0,%1,%2,%3}, [%4];"
                 : "=r"(r[0]), "=r"(r[1]), "=r"(r[2]), "=r"(r[3]) : "r"(addr));
}
__device__ __forceinline__ void mma16816(float* c, const uint32_t* a, uint32_t b0, uint32_t b1) {
    asm volatile("mma.sync.aligned.m16n8k16.row.col.f32.bf16.bf16.f32 "
                 "{%0,%1,%2,%3}, {%4,%5,%6,%7}, {%8,%9}, {%0,%1,%2,%3};"
                 : "+f"(c[0]), "+f"(c[1]), "+f"(c[2]), "+f"(c[3])
                 : "r"(a[0]), "r"(a[1]), "r"(a[2]), "r"(a[3]), "r"(b0), "r"(b1));
}
__device__ __forceinline__ void sims_load(uint32_t sbase, const __nv_bfloat16* Ag,
                                          const __nv_bfloat16* Bg, int c, int tid) {
#pragma unroll
    for (int q = 0; q < 16; q++) {
        int seg = tid + 128 * q;
        int h = seg >> 10;
        int rs = seg & 1023;
        int r = rs >> 3, s8 = rs & 7;
        uint32_t dst = sbase + (uint32_t)h * 16384 + r * 128 + ((s8 ^ (r & 7)) << 4);
        const __nv_bfloat16* G = h ? Bg : Ag;
        const char* src = (const char*)(G + (size_t)r * 512 + c * 64 + s8 * 8);
        asm volatile("cp.async.cg.shared.global [%0], [%1], 16;"
                     :: "r"(dst), "l"(src) : "memory");
    }
    asm volatile("cp.async.commit_group;" ::: "memory");
}
__device__ __forceinline__ void gload(uint32_t dst_base, const __nv_bfloat16* G,
                                      int k0, int tid) {
#pragma unroll
    for (int q = 0; q < 4; q++) {
        int seg = tid + 256 * q;
        int r = seg >> 3, s8 = seg & 7;
        uint32_t dst = dst_base + r * 128 + ((s8 ^ (r & 7)) << 4);
        const char* src = (const char*)(G + (size_t)r * 256 + k0 + s8 * 8);
        asm volatile("cp.async.cg.shared.global [%0], [%1], 16;"
                     :: "r"(dst), "l"(src) : "memory");
    }
}
#define SIMS_SMEM 66048

// ======== sims: 128 threads, 4 warps x (64x64) tiles ========
__global__ void __launch_bounds__(128, 2) k_mma_sims() {
    int idx = blockIdx.x;
    int bj = (int)((sqrtf(8.f * idx + 1.f) - 1.f) * 0.5f);
    while ((bj + 1) * (bj + 2) / 2 <= idx) bj++;
    while (bj * (bj + 1) / 2 > idx) bj--;
    int bi = idx - bj * (bj + 1) / 2;           // bi <= bj
    extern __shared__ char smem[];
    uint32_t sb = smem_u32(smem);
    int tid = threadIdx.x;
    int lane = tid & 31, w = tid >> 5;
    int wm = (w & 1) * 64, wn = (w >> 1) * 64;

    const __nv_bfloat16* Ag = d_hb + (size_t)bi * 128 * 512;
    const __nv_bfloat16* Bg = d_hb + (size_t)bj * 128 * 512;

    float acc[4][8][4];
#pragma unroll
    for (int mt = 0; mt < 4; mt++)
#pragma unroll
        for (int nt = 0; nt < 8; nt++)
#pragma unroll
            for (int e = 0; e < 4; e++) acc[mt][nt][e] = 0.f;

    sims_load(sb, Ag, Bg, 0, tid);
    int lr = lane & 15, lks = lane >> 4;
    for (int c = 0; c < 8; c++) {
        if (c < 7) sims_load(sb + ((c + 1) & 1) * 32768, Ag, Bg, c + 1, tid);
        if (c < 7) asm volatile("cp.async.wait_group 1;" ::: "memory");
        else       asm volatile("cp.async.wait_group 0;" ::: "memory");
        __syncthreads();
        uint32_t aB = sb + (c & 1) * 32768, bB = aB + 16384;
#pragma unroll
        for (int ks = 0; ks < 4; ks++) {
            int segk = ks * 2 + lks;
            uint32_t a[4][4], b[4][4];
#pragma unroll
            for (int mt = 0; mt < 4; mt++) {
                int r = wm + mt * 16 + lr;
                ldsm4(a[mt], aB + r * 128 + ((segk ^ (r & 7)) << 4));
            }
#pragma unroll
            for (int bt = 0; bt < 4; bt++) {
                int r = wn + bt * 16 + lr;
                ldsm4(b[bt], bB + r * 128 + ((segk ^ (r & 7)) << 4));
            }
#pragma unroll
            for (int mt = 0; mt < 4; mt++)
#pragma unroll
                for (int nt = 0; nt < 8; nt++)
                    mma16816(acc[mt][nt], a[mt], b[nt >> 1][nt & 1], b[nt >> 1][(nt & 1) + 2]);
        }
        __syncthreads();
    }
    float* sf = (float*)smem;
    int g = lane >> 2, tq = lane & 3;
#pragma unroll
    for (int mt = 0; mt < 4; mt++)
#pragma unroll
        for (int nt = 0; nt < 8; nt++) {
            int r0 = wm + mt * 16 + g, c0 = wn + nt * 8 + tq * 2;
            sf[r0 * 129 + c0]           = acc[mt][nt][0];
            sf[r0 * 129 + c0 + 1]       = acc[mt][nt][1];
            sf[(r0 + 8) * 129 + c0]     = acc[mt][nt][2];
            sf[(r0 + 8) * 129 + c0 + 1] = acc[mt][nt][3];
        }
    __syncthreads();
    size_t gi0 = (size_t)bi * 128, gj0 = (size_t)bj * 128;
    if (bi != bj) {
        for (int it = tid; it < 128 * 64; it += 128) {
            int r = it >> 6, c2 = (it & 63) * 2;
            __nv_bfloat162 p = __floats2bfloat162_rn(sf[r * 129 + c2], sf[r * 129 + c2 + 1]);
            *(__nv_bfloat162*)&d_simh[(gi0 + r) * NN + gj0 + c2] = p;
        }
        for (int it = tid; it < 128 * 64; it += 128) {
            int j = it >> 6, i2 = (it & 63) * 2;
            __nv_bfloat162 p = __floats2bfloat162_rn(sf[i2 * 129 + j], sf[(i2 + 1) * 129 + j]);
            *(__nv_bfloat162*)&d_simh[(gj0 + j) * NN + gi0 + i2] = p;
        }
    } else {
        for (int it = tid; it < 128 * 64; it += 128) {
            int r = it >> 6, c2 = (it & 63) * 2;
            float v0 = (c2 >= r)     ? sf[r * 129 + c2]     : sf[c2 * 129 + r];
            float v1 = (c2 + 1 >= r) ? sf[r * 129 + c2 + 1] : sf[(c2 + 1) * 129 + r];
            __nv_bfloat162 p = __floats2bfloat162_rn(v0, v1);
            *(__nv_bfloat162*)&d_simh[(gi0 + r) * NN + gj0 + c2] = p;
        }
    }
}

// -------- topk: max-relative bins + prefilter + exact rescore --------
__global__ void k_topk(const float* __restrict__ alphap) {
    int row = blockIdx.x, t = threadIdx.x;
    int w = t >> 5, lane = t & 31;
    const uint4* srow = (const uint4*)(d_simh + (size_t)row * NN);
    uint32_t kp[16];
#pragma unroll
    for (int q = 0; q < 4; q++) {
        uint4 r4 = srow[q * 256 + t];
        uint32_t rr[4] = {r4.x, r4.y, r4.z, r4.w};
#pragma unroll
        for (int u = 0; u < 4; u++)
            kp[q * 4 + u] = bf16key(rr[u] & 0xFFFFu) | (bf16key(rr[u] >> 16) << 16);
    }
    __shared__ int hist[256];
    __shared__ int scn[256];
    __shared__ uint32_t sMax[8];
    __shared__ int sB, cnum;
    __shared__ int   cand[CANDCAP];
    __shared__ float cex[CANDCAP];
    hist[t] = 0;
    if (t == 0) { cnum = 0; sB = 255; }
    uint32_t mk = 0;
#pragma unroll
    for (int q = 0; q < 16; q++) {
        uint32_t a = kp[q] & 0xFFFFu, b2 = kp[q] >> 16;
        mk = max(mk, max(a, b2));
    }
#pragma unroll
    for (int o = 16; o > 0; o >>= 1)
        mk = max(mk, __shfl_xor_sync(0xffffffffu, mk, o));
    if (lane == 0) sMax[w] = mk;
    __syncthreads();
    uint32_t Kmax = sMax[0];
#pragma unroll
    for (int q = 1; q < 8; q++) Kmax = max(Kmax, sMax[q]);
#pragma unroll
    for (int q = 0; q < 16; q++) {
        uint32_t d0 = (Kmax - (kp[q] & 0xFFFFu)) >> 2;
        uint32_t d1 = (Kmax - (kp[q] >> 16)) >> 2;
        if (d0 < 256) atomicAdd(&hist[d0], 1);
        if (d1 < 256) atomicAdd(&hist[d1], 1);
    }
    __syncthreads();
    int hv = hist[t];
    scn[t] = hv;
    __syncthreads();
    for (int off = 1; off < 256; off <<= 1) {
        int v = (t >= off) ? scn[t - off] : 0;
        __syncthreads();
        scn[t] += v;
        __syncthreads();
    }
    if (scn[t] >= 32 && scn[t] - hv < 32) sB = t;
    __syncthreads();
    int B = sB;
#pragma unroll
    for (int q = 0; q < 16; q++) {
        uint32_t d0 = (Kmax - (kp[q] & 0xFFFFu)) >> 2;
        uint32_t d1 = (Kmax - (kp[q] >> 16)) >> 2;
        int qq = q >> 2, u = q & 3;
        int colbase = qq * 2048 + t * 8 + u * 2;
        if ((int)d0 <= B) { int pos = atomicAdd(&cnum, 1); if (pos < CANDCAP) cand[pos] = colbase; }
        if ((int)d1 <= B) { int pos = atomicAdd(&cnum, 1); if (pos < CANDCAP) cand[pos] = colbase + 1; }
    }
    __syncthreads();
    int nc = min(cnum, CANDCAP);
    const float* hr = d_hn + (size_t)row * 512;
    for (int c = w; c < nc; c += 8) {
        const float* hj = d_hn + (size_t)cand[c] * 512;
        float s = 0.f;
#pragma unroll
        for (int e = 0; e < 16; e++) s += hr[lane + e * 32] * hj[lane + e * 32];
        s = warp_sum(s);
        if (lane == 0) cex[c] = s;
    }
    __syncthreads();
    if (t < nc) {
        float myv = cex[t]; int myi = cand[t];
        int rank = 0;
        for (int c = 0; c < nc; c++) {
            float v = cex[c]; int ci = cand[c];
            if (v > myv || (v == myv && ci < myi)) rank++;
        }
        if (rank < KT) {
            d_tidx[row * KT + rank] = myi;
            d_tval[row * KT + rank] = (1.f - *alphap) * fmaxf(myv, 0.f);
        }
    }
}

// -------- kNN symmetric CSR build --------
__global__ void k_kcount() {
    int w = blockIdx.x * 256 + threadIdx.x;
    if (w >= NN * KT) return;
    int i = w / KT, j = d_tidx[w];
    bool found = false;
    const int* tj = d_tidx + j * KT;
#pragma unroll
    for (int q = 0; q < KT; q++) found |= (tj[q] == i);
    atomicAdd(&d_kcnt[i], 1);
    d_kmut[w] = found;
    if (!found) atomicAdd(&d_kcnt[j], 1);
}
__global__ void k_kscan() {
    __shared__ int bs[256];
    int t = threadIdx.x;
    int loc[32]; int s = 0;
#pragma unroll
    for (int q = 0; q < 32; q++) {
        loc[q] = d_kcnt[t * 32 + q];
        d_kcnt[t * 32 + q] = 0;
        s += loc[q];
    }
    bs[t] = s; __syncthreads();
    for (int off = 1; off < 256; off <<= 1) {
        int v = (t >= off) ? bs[t - off] : 0;
        __syncthreads();
        bs[t] += v;
        __syncthreads();
    }
    int run = bs[t] - s;
#pragma unroll
    for (int q = 0; q < 32; q++) {
        int i = t * 32 + q;
        d_kptr[i] = run; d_kcur[i] = run;
        run += loc[q];
    }
    if (t == 255) d_kptr[NN] = run;
}
__global__ void k_kfill() {
    int w = blockIdx.x * 256 + threadIdx.x;
    if (w >= NN * KT) return;
    int i = w / KT, j = d_tidx[w];
    float v = d_tval[w];
    int pos = atomicAdd(&d_kcur[i], 1);
    d_kidx[pos] = j; d_kval[pos] = v;
    if (!d_kmut[w]) {
        int pos2 = atomicAdd(&d_kcur[j], 1);
        d_kidx[pos2] = i; d_kval[pos2] = v;
    }
}

// -------- bf16 split GEMM: C[8192,256] = A @ W (3-term hi/lo) --------
template <int L>
__global__ void __launch_bounds__(256) k_gemm_bf16() {
    int bn = blockIdx.x, bm = blockIdx.y;
    extern __shared__ char smem[];
    uint32_t sb = smem_u32(smem);
    int tid = threadIdx.x, lane = tid & 31, w = tid >> 5;
    int wm = (w & 1) * 64, wn = (w >> 1) * 32;
    const __nv_bfloat16* Ah = (L ? d_h1h : d_feah) + (size_t)bm * 128 * 256;
    const __nv_bfloat16* Al = (L ? d_h1l : d_feal) + (size_t)bm * 128 * 256;
    const __nv_bfloat16* Bh = (L ? d_w2h : d_w1h) + (size_t)bn * 128 * 256;
    const __nv_bfloat16* Bl = (L ? d_w2l : d_w1l) + (size_t)bn * 128 * 256;
    float* C = L ? d_hw : d_xw;

    float acc[4][4][4];
#pragma unroll
    for (int mt = 0; mt < 4; mt++)
#pragma unroll
        for (int nt = 0; nt < 4; nt++)
#pragma unroll
            for (int e = 0; e < 4; e++) acc[mt][nt][e] = 0.f;

    int lr = lane & 15, lks = lane >> 4;
    for (int c = 0; c < 4; c++) {
        int k0 = c * 64;
        gload(sb,         Ah, k0, tid);
        gload(sb + 16384, Al, k0, tid);
        gload(sb + 32768, Bh, k0, tid);
        gload(sb + 49152, Bl, k0, tid);
        asm volatile("cp.async.commit_group;" ::: "memory");
        asm volatile("cp.async.wait_group 0;" ::: "memory");
        __syncthreads();
#pragma unroll
        for (int ks = 0; ks < 4; ks++) {
            int segk = ks * 2 + lks;
            uint32_t a[4][4], bh[2][4], bl[2][4];
#pragma unroll
            for (int bt = 0; bt < 2; bt++) {
                int r = wn + bt * 16 + lr;
                uint32_t off = r * 128 + ((segk ^ (r & 7)) << 4);
                ldsm4(bh[bt], sb + 32768 + off);
                ldsm4(bl[bt], sb + 49152 + off);
            }
#pragma unroll
            for (int mt = 0; mt < 4; mt++) {
                int r = wm + mt * 16 + lr;
                ldsm4(a[mt], sb + r * 128 + ((segk ^ (r & 7)) << 4));
            }
#pragma unroll
            for (int mt = 0; mt < 4; mt++)
#pragma unroll
                for (int nt = 0; nt < 4; nt++) {
                    mma16816(acc[mt][nt], a[mt], bh[nt >> 1][nt & 1], bh[nt >> 1][(nt & 1) + 2]);
                    mma16816(acc[mt][nt], a[mt], bl[nt >> 1][nt & 1], bl[nt >> 1][(nt & 1) + 2]);
                }
#pragma unroll
            for (int mt = 0; mt < 4; mt++) {
                int r = wm + mt * 16 + lr;
                ldsm4(a[mt], sb + 16384 + r * 128 + ((segk ^ (r & 7)) << 4));
            }
#pragma unroll
            for (int mt = 0; mt < 4; mt++)
#pragma unroll
                for (int nt = 0; nt < 4; nt++)
                    mma16816(acc[mt][nt], a[mt], bh[nt >> 1][nt & 1], bh[nt >> 1][(nt & 1) + 2]);
        }
        __syncthreads();
    }
    float* sf = (float*)smem;
    int g = lane >> 2, tq = lane & 3;
#pragma unroll
    for (int mt = 0; mt < 4; mt++)
#pragma unroll
        for (int nt = 0; nt < 4; nt++) {
            int r0 = wm + mt * 16 + g, c0 = wn + nt * 8 + tq * 2;
            sf[r0 * 129 + c0]           = acc[mt][nt][0];
            sf[r0 * 129 + c0 + 1]       = acc[mt][nt][1];
            sf[(r0 + 8) * 129 + c0]     = acc[mt][nt][2];
            sf[(r0 + 8) * 129 + c0 + 1] = acc[mt][nt][3];
        }
    __syncthreads();
    size_t gm0 = (size_t)bm * 128;
    int nc0 = bn * 128;
    for (int it = tid; it < 128 * 128; it += 256) {
        int r = it >> 7, col = it & 127;
        C[(gm0 + r) * 256 + nc0 + col] = sf[r * 129 + col];
    }
}

// -------- gather-based A_tot @ X (unroll 4) --------
template <int L>
__global__ void k_spmm_gather(const float* __restrict__ alphap) {
    int gw = (blockIdx.x * 256 + threadIdx.x) >> 5, lane = threadIdx.x & 31;
    if (gw >= NN) return;
    const float* X = (L == 0) ? d_xw : d_hw;
    float* out = (L == 0) ? d_h1 : d_emb;
    float alpha = *alphap;
    float di = d_dinv[gw];
    const float4* xr = (const float4*)(X + (size_t)gw * 256);
    float4 x0 = xr[lane], x1 = xr[lane + 32];
    float sc = di * di;
    float4 a0 = make_float4(sc*x0.x, sc*x0.y, sc*x0.z, sc*x0.w);
    float4 a1 = make_float4(sc*x1.x, sc*x1.y, sc*x1.z, sc*x1.w);
    int b = d_rptr[gw], e = d_rptr[gw + 1];
    int p = b;
    for (; p + 3 < e; p += 4) {
        float w0 = d_cw[p], w1 = d_cw[p+1], w2 = d_cw[p+2], w3 = d_cw[p+3];
        const float4* s0 = (const float4*)(X + (size_t)d_csrc[p] * 256);
        const float4* s1 = (const float4*)(X + (size_t)d_csrc[p+1] * 256);
        const float4* s2 = (const float4*)(X + (size_t)d_csrc[p+2] * 256);
        const float4* s3 = (const float4*)(X + (size_t)d_csrc[p+3] * 256);
        float4 v00 = s0[lane], v01 = s0[lane+32];
        float4 v10 = s1[lane], v11 = s1[lane+32];
        float4 v20 = s2[lane], v21 = s2[lane+32];
        float4 v30 = s3[lane], v31 = s3[lane+32];
        fma4(a0, w0, v00); fma4(a1, w0, v01);
        fma4(a0, w1, v10); fma4(a1, w1, v11);
        fma4(a0, w2, v20); fma4(a1, w2, v21);
        fma4(a0, w3, v30); fma4(a1, w3, v31);
    }
    for (; p < e; p++) {
        float wv = d_cw[p];
        const float4* xs = (const float4*)(X + (size_t)d_csrc[p] * 256);
        fma4(a0, wv, xs[lane]); fma4(a1, wv, xs[lane + 32]);
    }
    a0.x*=alpha; a0.y*=alpha; a0.z*=alpha; a0.w*=alpha;
    a1.x*=alpha; a1.y*=alpha; a1.z*=alpha; a1.w*=alpha;
    int kb = d_kptr[gw], ke = d_kptr[gw + 1];
    p = kb;
    for (; p + 3 < ke; p += 4) {
        float w0 = d_kval[p], w1 = d_kval[p+1], w2 = d_kval[p+2], w3 = d_kval[p+3];
        const float4* s0 = (const float4*)(X + (size_t)d_kidx[p] * 256);
        const float4* s1 = (const float4*)(X + (size_t)d_kidx[p+1] * 256);
        const float4* s2 = (const float4*)(X + (size_t)d_kidx[p+2] * 256);
        const float4* s3 = (const float4*)(X + (size_t)d_kidx[p+3] * 256);
        float4 v00 = s0[lane], v01 = s0[lane+32];
        float4 v10 = s1[lane], v11 = s1[lane+32];
        float4 v20 = s2[lane], v21 = s2[lane+32];
        float4 v30 = s3[lane], v31 = s3[lane+32];
        fma4(a0, w0, v00); fma4(a1, w0, v01);
        fma4(a0, w1, v10); fma4(a1, w1, v11);
        fma4(a0, w2, v20); fma4(a1, w2, v21);
        fma4(a0, w3, v30); fma4(a1, w3, v31);
    }
    for (; p < ke; p++) {
        float v = d_kval[p];
        const float4* xs = (const float4*)(X + (size_t)d_kidx[p] * 256);
        fma4(a0, v, xs[lane]); fma4(a1, v, xs[lane + 32]);
    }
    if (L == 0) {
        a0.x=fmaxf(a0.x,0.f); a0.y=fmaxf(a0.y,0.f); a0.z=fmaxf(a0.z,0.f); a0.w=fmaxf(a0.w,0.f);
        a1.x=fmaxf(a1.x,0.f); a1.y=fmaxf(a1.y,0.f); a1.z=fmaxf(a1.z,0.f); a1.w=fmaxf(a1.w,0.f);
        uint2* h1h = (uint2*)(d_h1h + (size_t)gw * 256);
        uint2* h1l = (uint2*)(d_h1l + (size_t)gw * 256);
        uint2 p0 = pack_bf16x4(a0);
        uint2 p1 = pack_bf16x4(a1);
        h1h[lane] = p0; h1h[lane + 32] = p1;
        __nv_bfloat162* pv0 = (__nv_bfloat162*)&p0;
        __nv_bfloat162* pv1 = (__nv_bfloat162*)&p1;
        float4 r0 = make_float4(a0.x - __bfloat162float(__low2bfloat16(pv0[0])),
                                a0.y - __bfloat162float(__high2bfloat16(pv0[0])),
                                a0.z - __bfloat162float(__low2bfloat16(pv0[1])),
                                a0.w - __bfloat162float(__high2bfloat16(pv0[1])));
        float4 r1 = make_float4(a1.x - __bfloat162float(__low2bfloat16(pv1[0])),
                                a1.y - __bfloat162float(__high2bfloat16(pv1[0])),
                                a1.z - __bfloat162float(__low2bfloat16(pv1[1])),
                                a1.w - __bfloat162float(__high2bfloat16(pv1[1])));
        h1l[lane] = pack_bf16x4(r0); h1l[lane + 32] = pack_bf16x4(r1);
    }
    float4* orow = (float4*)(out + (size_t)gw * 256);
    orow[lane] = a0; orow[lane + 32] = a1;
}

// -------- classification --------
__global__ void k_cls_scatter(const int* __restrict__ labels, const int* __restrict__ nidx) {
    int w = (blockIdx.x*256+threadIdx.x) >> 5, lane = threadIdx.x & 31;
    if (w >= NSEL) return;
    int lbl = labels[w];
    const float4* er = (const float4*)(d_emb + (size_t)nidx[w]*HIDD);
    float4* sr = (float4*)(d_sums + lbl*HIDD);
#pragma unroll
    for (int q = 0; q < 2; q++) {
        int f = lane + 32*q; float4 v = er[f];
        red4(&sr[f], v.x, v.y, v.z, v.w);
    }
    if (lane == 0) atomicAdd(&d_cnt[lbl], 1.f);
}
__global__ void k_proto() {
    int c = blockIdx.x, t = threadIdx.x;
    float cnt = d_cnt[c];
    float sm = d_sums[c*HIDD+t];
    float p = sm / fmaxf(cnt, 1.f);
    __shared__ float red[256];
    red[t] = p*p;
    __syncthreads();
    for (int s = 128; s > 0; s >>= 1) { if (t < s) red[t] += red[t+s]; __syncthreads(); }
    d_pn[c*HIDD+t] = p / (sqrtf(red[0]) + EPSF);
    d_sums[c*HIDD+t] = 0.f;
    if (t == 0) d_cnt[c] = 0.f;
}
__global__ void k_out(const int* __restrict__ nidx, float* __restrict__ out) {
    int w = (blockIdx.x*256+threadIdx.x) >> 5, lane = threadIdx.x & 31;
    if (w >= NSEL) return;
    const float* er = d_emb + (size_t)nidx[w]*HIDD;
    float v[8]; float ss = 0.f;
#pragma unroll
    for (int q = 0; q < 8; q++) { v[q] = er[lane+32*q]; ss += v[q]*v[q]; }
    ss = warp_sum(ss);
    float rn = 1.f / (sqrtf(ss) + EPSF);
#pragma unroll
    for (int c = 0; c < NCLS; c++) {
        float dp = 0.f;
#pragma unroll
        for (int q = 0; q < 8; q++) dp += v[q] * d_pn[c*HIDD + lane + 32*q];
        dp = warp_sum(dp);
        if (lane == 0) out[w*NCLS + c] = dp * rn * 5.0f;
    }
}

extern "C" void kernel_launch(void* const* d_in, const int* in_sizes, int n_in,
                              void* d_out, int out_size) {
    const float* x   = (const float*)d_in[0];
    const float* cw  = (const float*)d_in[1];
    const float* alp = (const float*)d_in[2];
    const float* ps  = (const float*)d_in[3];
    const float* st  = (const float*)d_in[4];
    const float* bal = (const float*)d_in[5];
    const float* W1  = (const float*)d_in[6];
    const float* W2  = (const float*)d_in[7];
    const int*   ei  = (const int*)d_in[8];
    const int*   lab = (const int*)d_in[9];
    const int*   nix = (const int*)d_in[10];
    float* out = (float*)d_out;
    const int* esrc = ei;
    const int* edst = ei + NE;

    cudaFuncSetAttribute(k_mma_sims, cudaFuncAttributeMaxDynamicSharedMemorySize, SIMS_SMEM);
    cudaFuncSetAttribute(k_gemm_bf16<0>, cudaFuncAttributeMaxDynamicSharedMemorySize, SIMS_SMEM);
    cudaFuncSetAttribute(k_gemm_bf16<1>, cudaFuncAttributeMaxDynamicSharedMemorySize, SIMS_SMEM);

    k_fea<<<NN*FIN/1024, 256>>>(x, cw, ps, st, edst, W1, W2);   // 2048 blocks, x4 per thread
    k_scan<<<1, 256>>>();
    k_fill<<<NE/256, 256>>>(esrc, edst);
    k_agg_h<<<NN/8, 256>>>(bal);
    k_mma_sims<<<2080, 128, SIMS_SMEM>>>();
    k_topk<<<NN, 256>>>(alp);
    k_kcount<<<(NN*KT+255)/256, 256>>>();
    k_kscan<<<1, 256>>>();
    k_kfill<<<(NN*KT+255)/256, 256>>>();

    k_gemm_bf16<0><<<dim3(2, 64), 256, SIMS_SMEM>>>();
    k_spmm_gather<0><<<NN/8, 256>>>(alp);
    k_gemm_bf16<1><<<dim3(2, 64), 256, SIMS_SMEM>>>();
    k_spmm_gather<1><<<NN/8, 256>>>(alp);

    k_cls_scatter<<<NSEL/8, 256>>>(lab, nix);
    k_proto<<<NCLS, 256>>>();
    k_out<<<NSEL/8, 256>>>(nix, out);
}

// round 14
// speedup vs baseline: 1.0219x; 1.0219x over previous
#include <cuda_runtime.h>
#include <cuda_bf16.h>
#include <math.h>
#include <float.h>
#include <stdint.h>

#define NN   8192
#define FIN  256
#define HIDD 256
#define NE   131072
#define KT   17
#define CANDCAP 96
#define NCLS 10
#define NSEL 4096
#define EPSF 1e-8f
#define NGEMM0 128
#define NTILES 2080

__device__ __align__(16) float d_fea[NN * FIN];
__device__ __align__(16) __nv_bfloat16 d_feah[NN * FIN];
__device__ __align__(16) __nv_bfloat16 d_feal[NN * FIN];
__device__ float d_dinv[NN];
__device__ int   d_cnt_e[NN];          // self-clean in k_scan
__device__ int   d_rptr[NN + 1];
__device__ int   d_cur[NN];
__device__ int   d_csrc[NE];
__device__ float d_cw[NE];
__device__ __align__(16) float d_hn[NN * 512];
__device__ __align__(16) __nv_bfloat16 d_hb[NN * 512];
__device__ __nv_bfloat16 d_simh[(size_t)NN * NN];
__device__ int   d_tidx[NN * KT];
__device__ float d_tval[NN * KT];
__device__ int   d_kcnt[NN];           // self-clean in k_kscan
__device__ int   d_kptr[NN + 1];
__device__ int   d_kcur[NN];
__device__ unsigned char d_kmut[NN * KT];
__device__ int   d_kidx[NN * KT * 2];
__device__ float d_kval[NN * KT * 2];
__device__ __align__(16) __nv_bfloat16 d_w1h[FIN * HIDD];
__device__ __align__(16) __nv_bfloat16 d_w1l[FIN * HIDD];
__device__ __align__(16) __nv_bfloat16 d_w2h[HIDD * HIDD];
__device__ __align__(16) __nv_bfloat16 d_w2l[HIDD * HIDD];
__device__ __align__(16) float d_xw[NN * HIDD];
__device__ __align__(16) float d_h1[NN * HIDD];
__device__ __align__(16) __nv_bfloat16 d_h1h[NN * HIDD];
__device__ __align__(16) __nv_bfloat16 d_h1l[NN * HIDD];
__device__ __align__(16) float d_hw[NN * HIDD];
__device__ __align__(16) float d_emb[NN * HIDD];
__device__ __align__(16) float d_sums[NCLS * HIDD]; // self-clean in k_proto
__device__ float d_cnt[NCLS];                       // self-clean in k_proto
__device__ float d_pn[NCLS * HIDD];

__device__ __forceinline__ float warp_sum(float v) {
#pragma unroll
    for (int o = 16; o > 0; o >>= 1) v += __shfl_xor_sync(0xffffffffu, v, o);
    return v;
}
__device__ __forceinline__ void red4(float4* addr, float a, float b, float c, float d) {
    asm volatile("red.global.add.v4.f32 [%0], {%1,%2,%3,%4};"
                 :: "l"(addr), "f"(a), "f"(b), "f"(c), "f"(d) : "memory");
}
__device__ __forceinline__ void fma4(float4& a, float w, const float4 v) {
    a.x += w * v.x; a.y += w * v.y; a.z += w * v.z; a.w += w * v.w;
}
__device__ __forceinline__ uint2 pack_bf16x4(float4 v) {
    __nv_bfloat162 lo = __floats2bfloat162_rn(v.x, v.y);
    __nv_bfloat162 hi = __floats2bfloat162_rn(v.z, v.w);
    uint2 r;
    r.x = *reinterpret_cast<uint32_t*>(&lo);
    r.y = *reinterpret_cast<uint32_t*>(&hi);
    return r;
}
__device__ __forceinline__ uint32_t bf16key(uint32_t b) {
    return (b & 0x8000u) ? (~b & 0xFFFFu) : (b | 0x8000u);
}

// -------- fea = elu(...) + hi/lo split + degree count + fused wpack --------
__global__ void k_fea(const float* __restrict__ x, const float* __restrict__ cw,
                      const float* __restrict__ ps, const float* __restrict__ st,
                      const int* __restrict__ dst,
                      const float* __restrict__ W1, const float* __restrict__ W2) {
    int idx = blockIdx.x * 256 + threadIdx.x;
    int f = idx & (FIN - 1);
    float z = x[idx] * (cw[0] * ps[f] + cw[1] * st[f]);
    float r = z > 0.f ? z : expm1f(z);
    d_fea[idx] = r;
    __nv_bfloat16 hi = __float2bfloat16(r);
    d_feah[idx] = hi;
    d_feal[idx] = __float2bfloat16(r - __bfloat162float(hi));
    if (idx < NE) {
        atomicAdd(&d_cnt_e[dst[idx]], 1);
        int wsel = idx >> 16;
        int e = idx & 0xFFFF;
        int k = e >> 8, n = e & 255;
        float v = (wsel ? W2 : W1)[e];
        __nv_bfloat16 wh = __float2bfloat16(v);
        (wsel ? d_w2h : d_w1h)[n * 256 + k] = wh;
        (wsel ? d_w2l : d_w1l)[n * 256 + k] = __float2bfloat16(v - __bfloat162float(wh));
    }
}
// -------- scan (+self-clean counts) --------
__global__ void k_scan() {
    __shared__ int bs[256];
    int t = threadIdx.x;
    int loc[32]; int s = 0;
#pragma unroll
    for (int q = 0; q < 32; q++) {
        loc[q] = d_cnt_e[t * 32 + q];
        d_cnt_e[t * 32 + q] = 0;
        s += loc[q];
    }
    bs[t] = s; __syncthreads();
    for (int off = 1; off < 256; off <<= 1) {
        int v = (t >= off) ? bs[t - off] : 0;
        __syncthreads();
        bs[t] += v;
        __syncthreads();
    }
    int run = bs[t] - s;
#pragma unroll
    for (int q = 0; q < 32; q++) {
        int i = t * 32 + q;
        d_rptr[i] = run; d_cur[i] = run;
        d_dinv[i] = rsqrtf((float)(loc[q] + 1));
        run += loc[q];
    }
    if (t == 255) d_rptr[NN] = run;
}
__global__ void k_fill(const int* __restrict__ src, const int* __restrict__ dst) {
    int e = blockIdx.x * 256 + threadIdx.x;
    if (e >= NE) return;
    int s = src[e], d = dst[e];
    int pos = atomicAdd(&d_cur[d], 1);
    d_csrc[pos] = s;
    d_cw[pos] = d_dinv[s] * d_dinv[d];
}
// -------- fused aggregate-gather + h-normalize + bf16 --------
__global__ void k_agg_h(const float* __restrict__ bal) {
    int gw = (blockIdx.x * 256 + threadIdx.x) >> 5, lane = threadIdx.x & 31;
    if (gw >= NN) return;
    float di = d_dinv[gw];
    const float4* fr = (const float4*)(d_fea + (size_t)gw * 256);
    float4 f0 = fr[lane], f1 = fr[lane + 32];
    float sc = di * di;
    float4 a0 = make_float4(sc*f0.x, sc*f0.y, sc*f0.z, sc*f0.w);
    float4 a1 = make_float4(sc*f1.x, sc*f1.y, sc*f1.z, sc*f1.w);
    int b = d_rptr[gw], e = d_rptr[gw + 1];
    int p = b;
    for (; p + 1 < e; p += 2) {
        float w0 = d_cw[p], w1 = d_cw[p + 1];
        const float4* s0 = (const float4*)(d_fea + (size_t)d_csrc[p] * 256);
        const float4* s1 = (const float4*)(d_fea + (size_t)d_csrc[p + 1] * 256);
        float4 v00 = s0[lane], v01 = s0[lane + 32];
        float4 v10 = s1[lane], v11 = s1[lane + 32];
        fma4(a0, w0, v00); fma4(a1, w0, v01);
        fma4(a0, w1, v10); fma4(a1, w1, v11);
    }
    if (p < e) {
        float wv = d_cw[p];
        const float4* fs = (const float4*)(d_fea + (size_t)d_csrc[p] * 256);
        fma4(a0, wv, fs[lane]); fma4(a1, wv, fs[lane + 32]);
    }
    const float4* bb = (const float4*)bal;
    float4 bA = bb[lane], bB = bb[lane + 32], bC = bb[64 + lane], bD = bb[96 + lane];
    float4 hA = make_float4(f0.x*bA.x, f0.y*bA.y, f0.z*bA.z, f0.w*bA.w);
    float4 hB = make_float4(f1.x*bB.x, f1.y*bB.y, f1.z*bB.z, f1.w*bB.w);
    float4 hC = make_float4(a0.x*bC.x, a0.y*bC.y, a0.z*bC.z, a0.w*bC.w);
    float4 hD = make_float4(a1.x*bD.x, a1.y*bD.y, a1.z*bD.z, a1.w*bD.w);
    float ss = hA.x*hA.x+hA.y*hA.y+hA.z*hA.z+hA.w*hA.w
             + hB.x*hB.x+hB.y*hB.y+hB.z*hB.z+hB.w*hB.w
             + hC.x*hC.x+hC.y*hC.y+hC.z*hC.z+hC.w*hC.w
             + hD.x*hD.x+hD.y*hD.y+hD.z*hD.z+hD.w*hD.w;
    ss = warp_sum(ss);
    float rn = 1.f / (sqrtf(ss) + EPSF);
    hA.x*=rn; hA.y*=rn; hA.z*=rn; hA.w*=rn;
    hB.x*=rn; hB.y*=rn; hB.z*=rn; hB.w*=rn;
    hC.x*=rn; hC.y*=rn; hC.z*=rn; hC.w*=rn;
    hD.x*=rn; hD.y*=rn; hD.z*=rn; hD.w*=rn;
    float4* hr = (float4*)(d_hn + (size_t)gw * 512);
    hr[lane] = hA; hr[lane + 32] = hB; hr[64 + lane] = hC; hr[96 + lane] = hD;
    uint2* hb = (uint2*)(d_hb + (size_t)gw * 512);
    hb[lane] = pack_bf16x4(hA); hb[lane + 32] = pack_bf16x4(hB);
    hb[64 + lane] = pack_bf16x4(hC); hb[96 + lane] = pack_bf16x4(hD);
}

// ======== mma helpers ========
__device__ __forceinline__ uint32_t smem_u32(const void* p) {
    uint32_t a;
    asm("{ .reg .u64 t; cvta.to.shared.u64 t, %1; cvt.u32.u64 %0, t; }" : "=r"(a) : "l"(p));
    return a;
}
__device__ __forceinline__ void ldsm4(uint32_t* r, uint32_t addr) {
    asm volatile("ldmatrix.sync.aligned.m8n8.x4.shared.b16 {%0,%1,%2,%3}, [%4];"
                 : "=r"(r[0]), "=r"(r[1]), "=r"(r[2]), "=r"(r[3]) : "r"(addr));
}
__device__ __forceinline__ void mma16816(float* c, const uint32_t* a, uint32_t b0, uint32_t b1) {
    asm volatile("mma.sync.aligned.m16n8k16.row.col.f32.bf16.bf16.f32 "
                 "{%0,%1,%2,%3}, {%4,%5,%6,%7}, {%8,%9}, {%0,%1,%2,%3};"
                 : "+f"(c[0]), "+f"(c[1]), "+f"(c[2]), "+f"(c[3])
                 : "r"(a[0]), "r"(a[1]), "r"(a[2]), "r"(a[3]), "r"(b0), "r"(b1));
}
// A 128x64 + B 128x64 stage load from row-stride-512 matrices (256 threads)
__device__ __forceinline__ void sims_load(uint32_t sbase, const __nv_bfloat16* Ag,
                                          const __nv_bfloat16* Bg, int c, int tid) {
#pragma unroll
    for (int h = 0; h < 2; h++) {
        const __nv_bfloat16* G = h ? Bg : Ag;
        uint32_t base = sbase + (uint32_t)h * 16384;
#pragma unroll
        for (int q = 0; q < 4; q++) {
            int seg = tid + 256 * q;
            int r = seg >> 3, s8 = seg & 7;
            uint32_t dst = base + r * 128 + ((s8 ^ (r & 7)) << 4);
            const char* src = (const char*)(G + (size_t)r * 512 + c * 64 + s8 * 8);
            asm volatile("cp.async.cg.shared.global [%0], [%1], 16;"
                         :: "r"(dst), "l"(src) : "memory");
        }
    }
    asm volatile("cp.async.commit_group;" ::: "memory");
}
// 128 rows x 64 bf16 tile from a row-stride-256 matrix (256 threads)
__device__ __forceinline__ void gload(uint32_t dst_base, const __nv_bfloat16* G,
                                      int k0, int tid) {
#pragma unroll
    for (int q = 0; q < 4; q++) {
        int seg = tid + 256 * q;
        int r = seg >> 3, s8 = seg & 7;
        uint32_t dst = dst_base + r * 128 + ((s8 ^ (r & 7)) << 4);
        const char* src = (const char*)(G + (size_t)r * 256 + k0 + s8 * 8);
        asm volatile("cp.async.cg.shared.global [%0], [%1], 16;"
                     :: "r"(dst), "l"(src) : "memory");
    }
}
#define SIMS_SMEM 66048

// -------- shared gemm body: C[128x256 tile] = A @ W (3-term hi/lo bf16) --------
__device__ __forceinline__ void gemm_body(const __nv_bfloat16* Ah, const __nv_bfloat16* Al,
                                          const __nv_bfloat16* Bh, const __nv_bfloat16* Bl,
                                          float* C, size_t gm0, int nc0,
                                          char* smem, uint32_t sb, int tid) {
    int lane = tid & 31, w = tid >> 5;
    int wm = (w & 1) * 64, wn = (w >> 1) * 32;
    float acc[4][4][4];
#pragma unroll
    for (int mt = 0; mt < 4; mt++)
#pragma unroll
        for (int nt = 0; nt < 4; nt++)
#pragma unroll
            for (int e = 0; e < 4; e++) acc[mt][nt][e] = 0.f;
    int lr = lane & 15, lks = lane >> 4;
    for (int c = 0; c < 4; c++) {
        int k0 = c * 64;
        gload(sb,         Ah, k0, tid);
        gload(sb + 16384, Al, k0, tid);
        gload(sb + 32768, Bh, k0, tid);
        gload(sb + 49152, Bl, k0, tid);
        asm volatile("cp.async.commit_group;" ::: "memory");
        asm volatile("cp.async.wait_group 0;" ::: "memory");
        __syncthreads();
#pragma unroll
        for (int ks = 0; ks < 4; ks++) {
            int segk = ks * 2 + lks;
            uint32_t a[4][4], bh[2][4], bl[2][4];
#pragma unroll
            for (int bt = 0; bt < 2; bt++) {
                int r = wn + bt * 16 + lr;
                uint32_t off = r * 128 + ((segk ^ (r & 7)) << 4);
                ldsm4(bh[bt], sb + 32768 + off);
                ldsm4(bl[bt], sb + 49152 + off);
            }
#pragma unroll
            for (int mt = 0; mt < 4; mt++) {
                int r = wm + mt * 16 + lr;
                ldsm4(a[mt], sb + r * 128 + ((segk ^ (r & 7)) << 4));
            }
#pragma unroll
            for (int mt = 0; mt < 4; mt++)
#pragma unroll
                for (int nt = 0; nt < 4; nt++) {
                    mma16816(acc[mt][nt], a[mt], bh[nt >> 1][nt & 1], bh[nt >> 1][(nt & 1) + 2]);
                    mma16816(acc[mt][nt], a[mt], bl[nt >> 1][nt & 1], bl[nt >> 1][(nt & 1) + 2]);
                }
#pragma unroll
            for (int mt = 0; mt < 4; mt++) {
                int r = wm + mt * 16 + lr;
                ldsm4(a[mt], sb + 16384 + r * 128 + ((segk ^ (r & 7)) << 4));
            }
#pragma unroll
            for (int mt = 0; mt < 4; mt++)
#pragma unroll
                for (int nt = 0; nt < 4; nt++)
                    mma16816(acc[mt][nt], a[mt], bh[nt >> 1][nt & 1], bh[nt >> 1][(nt & 1) + 2]);
        }
        __syncthreads();
    }
    float* sf = (float*)smem;
    int g = lane >> 2, tq = lane & 3;
#pragma unroll
    for (int mt = 0; mt < 4; mt++)
#pragma unroll
        for (int nt = 0; nt < 4; nt++) {
            int r0 = wm + mt * 16 + g, c0 = wn + nt * 8 + tq * 2;
            sf[r0 * 129 + c0]           = acc[mt][nt][0];
            sf[r0 * 129 + c0 + 1]       = acc[mt][nt][1];
            sf[(r0 + 8) * 129 + c0]     = acc[mt][nt][2];
            sf[(r0 + 8) * 129 + c0 + 1] = acc[mt][nt][3];
        }
    __syncthreads();
    for (int it = tid; it < 128 * 128; it += 256) {
        int r = it >> 7, col = it & 127;
        C[(gm0 + r) * 256 + nc0 + col] = sf[r * 129 + col];
    }
}

// ======== fused: gemm<0> blocks (idx < 128) + sims upper-tri tiles ========
__global__ void __launch_bounds__(256, 2) k_sims_gemm0() {
    int bidx = blockIdx.x;
    extern __shared__ char smem[];
    uint32_t sb = smem_u32(smem);
    int tid = threadIdx.x;
    if (bidx < NGEMM0) {
        int g = bidx;
        int bn = g & 1, bm = g >> 1;
        gemm_body(d_feah + (size_t)bm * 128 * 256, d_feal + (size_t)bm * 128 * 256,
                  d_w1h + (size_t)bn * 128 * 256, d_w1l + (size_t)bn * 128 * 256,
                  d_xw, (size_t)bm * 128, bn * 128, smem, sb, tid);
        return;
    }
    int idx = bidx - NGEMM0;
    int bj = (int)((sqrtf(8.f * idx + 1.f) - 1.f) * 0.5f);
    while ((bj + 1) * (bj + 2) / 2 <= idx) bj++;
    while (bj * (bj + 1) / 2 > idx) bj--;
    int bi = idx - bj * (bj + 1) / 2;           // bi <= bj
    int lane = tid & 31, w = tid >> 5;
    int wm = (w & 1) * 64, wn = (w >> 1) * 32;

    const __nv_bfloat16* Ag = d_hb + (size_t)bi * 128 * 512;
    const __nv_bfloat16* Bg = d_hb + (size_t)bj * 128 * 512;

    float acc[4][4][4];
#pragma unroll
    for (int mt = 0; mt < 4; mt++)
#pragma unroll
        for (int nt = 0; nt < 4; nt++)
#pragma unroll
            for (int e = 0; e < 4; e++) acc[mt][nt][e] = 0.f;

    sims_load(sb, Ag, Bg, 0, tid);
    int lr = lane & 15, lks = lane >> 4;
    for (int c = 0; c < 8; c++) {
        if (c < 7) sims_load(sb + ((c + 1) & 1) * 32768, Ag, Bg, c + 1, tid);
        if (c < 7) asm volatile("cp.async.wait_group 1;" ::: "memory");
        else       asm volatile("cp.async.wait_group 0;" ::: "memory");
        __syncthreads();
        uint32_t aB = sb + (c & 1) * 32768, bB = aB + 16384;
#pragma unroll
        for (int ks = 0; ks < 4; ks++) {
            int segk = ks * 2 + lks;
            uint32_t a[4][4], b[2][4];
#pragma unroll
            for (int mt = 0; mt < 4; mt++) {
                int r = wm + mt * 16 + lr;
                ldsm4(a[mt], aB + r * 128 + ((segk ^ (r & 7)) << 4));
            }
#pragma unroll
            for (int bt = 0; bt < 2; bt++) {
                int r = wn + bt * 16 + lr;
                ldsm4(b[bt], bB + r * 128 + ((segk ^ (r & 7)) << 4));
            }
#pragma unroll
            for (int mt = 0; mt < 4; mt++)
#pragma unroll
                for (int nt = 0; nt < 4; nt++)
                    mma16816(acc[mt][nt], a[mt], b[nt >> 1][nt & 1], b[nt >> 1][(nt & 1) + 2]);
        }
        __syncthreads();
    }
    float* sf = (float*)smem;
    int g = lane >> 2, tq = lane & 3;
#pragma unroll
    for (int mt = 0; mt < 4; mt++)
#pragma unroll
        for (int nt = 0; nt < 4; nt++) {
            int r0 = wm + mt * 16 + g, c0 = wn + nt * 8 + tq * 2;
            sf[r0 * 129 + c0]           = acc[mt][nt][0];
            sf[r0 * 129 + c0 + 1]       = acc[mt][nt][1];
            sf[(r0 + 8) * 129 + c0]     = acc[mt][nt][2];
            sf[(r0 + 8) * 129 + c0 + 1] = acc[mt][nt][3];
        }
    __syncthreads();
    size_t gi0 = (size_t)bi * 128, gj0 = (size_t)bj * 128;
    if (bi != bj) {
        for (int it = tid; it < 128 * 64; it += 256) {
            int r = it >> 6, c2 = (it & 63) * 2;
            __nv_bfloat162 p = __floats2bfloat162_rn(sf[r * 129 + c2], sf[r * 129 + c2 + 1]);
            *(__nv_bfloat162*)&d_simh[(gi0 + r) * NN + gj0 + c2] = p;
        }
        for (int it = tid; it < 128 * 64; it += 256) {
            int j = it >> 6, i2 = (it & 63) * 2;
            __nv_bfloat162 p = __floats2bfloat162_rn(sf[i2 * 129 + j], sf[(i2 + 1) * 129 + j]);
            *(__nv_bfloat162*)&d_simh[(gj0 + j) * NN + gi0 + i2] = p;
        }
    } else {
        for (int it = tid; it < 128 * 64; it += 256) {
            int r = it >> 6, c2 = (it & 63) * 2;
            float v0 = (c2 >= r)     ? sf[r * 129 + c2]     : sf[c2 * 129 + r];
            float v1 = (c2 + 1 >= r) ? sf[r * 129 + c2 + 1] : sf[(c2 + 1) * 129 + r];
            __nv_bfloat162 p = __floats2bfloat162_rn(v0, v1);
            *(__nv_bfloat162*)&d_simh[(gi0 + r) * NN + gj0 + c2] = p;
        }
    }
}

// -------- topk: max-relative bins + prefilter + exact rescore --------
__global__ void k_topk(const float* __restrict__ alphap) {
    int row = blockIdx.x, t = threadIdx.x;
    int w = t >> 5, lane = t & 31;
    const uint4* srow = (const uint4*)(d_simh + (size_t)row * NN);
    uint32_t kp[16];
#pragma unroll
    for (int q = 0; q < 4; q++) {
        uint4 r4 = srow[q * 256 + t];
        uint32_t rr[4] = {r4.x, r4.y, r4.z, r4.w};
#pragma unroll
        for (int u = 0; u < 4; u++)
            kp[q * 4 + u] = bf16key(rr[u] & 0xFFFFu) | (bf16key(rr[u] >> 16) << 16);
    }
    __shared__ int hist[256];
    __shared__ int scn[256];
    __shared__ uint32_t sMax[8];
    __shared__ int sB, cnum;
    __shared__ int   cand[CANDCAP];
    __shared__ float cex[CANDCAP];
    hist[t] = 0;
    if (t == 0) { cnum = 0; sB = 255; }
    uint32_t mk = 0;
#pragma unroll
    for (int q = 0; q < 16; q++) {
        uint32_t a = kp[q] & 0xFFFFu, b2 = kp[q] >> 16;
        mk = max(mk, max(a, b2));
    }
#pragma unroll
    for (int o = 16; o > 0; o >>= 1)
        mk = max(mk, __shfl_xor_sync(0xffffffffu, mk, o));
    if (lane == 0) sMax[w] = mk;
    __syncthreads();
    uint32_t Kmax = sMax[0];
#pragma unroll
    for (int q = 1; q < 8; q++) Kmax = max(Kmax, sMax[q]);
#pragma unroll
    for (int q = 0; q < 16; q++) {
        uint32_t d0 = (Kmax - (kp[q] & 0xFFFFu)) >> 2;
        uint32_t d1 = (Kmax - (kp[q] >> 16)) >> 2;
        if (d0 < 256) atomicAdd(&hist[d0], 1);
        if (d1 < 256) atomicAdd(&hist[d1], 1);
    }
    __syncthreads();
    int hv = hist[t];
    scn[t] = hv;
    __syncthreads();
    for (int off = 1; off < 256; off <<= 1) {
        int v = (t >= off) ? scn[t - off] : 0;
        __syncthreads();
        scn[t] += v;
        __syncthreads();
    }
    if (scn[t] >= 32 && scn[t] - hv < 32) sB = t;
    __syncthreads();
    int B = sB;
#pragma unroll
    for (int q = 0; q < 16; q++) {
        uint32_t d0 = (Kmax - (kp[q] & 0xFFFFu)) >> 2;
        uint32_t d1 = (Kmax - (kp[q] >> 16)) >> 2;
        int qq = q >> 2, u = q & 3;
        int colbase = qq * 2048 + t * 8 + u * 2;
        if ((int)d0 <= B) { int pos = atomicAdd(&cnum, 1); if (pos < CANDCAP) cand[pos] = colbase; }
        if ((int)d1 <= B) { int pos = atomicAdd(&cnum, 1); if (pos < CANDCAP) cand[pos] = colbase + 1; }
    }
    __syncthreads();
    int nc = min(cnum, CANDCAP);
    const float* hr = d_hn + (size_t)row * 512;
    for (int c = w; c < nc; c += 8) {
        const float* hj = d_hn + (size_t)cand[c] * 512;
        float s = 0.f;
#pragma unroll
        for (int e = 0; e < 16; e++) s += hr[lane + e * 32] * hj[lane + e * 32];
        s = warp_sum(s);
        if (lane == 0) cex[c] = s;
    }
    __syncthreads();
    if (t < nc) {
        float myv = cex[t]; int myi = cand[t];
        int rank = 0;
        for (int c = 0; c < nc; c++) {
            float v = cex[c]; int ci = cand[c];
            if (v > myv || (v == myv && ci < myi)) rank++;
        }
        if (rank < KT) {
            d_tidx[row * KT + rank] = myi;
            d_tval[row * KT + rank] = (1.f - *alphap) * fmaxf(myv, 0.f);
        }
    }
}

// -------- kNN symmetric CSR build --------
__global__ void k_kcount() {
    int w = (blockIdx.x * 256 + threadIdx.x) >> 5, lane = threadIdx.x & 31;
    if (w >= NN * KT) return;
    int i = w / KT, j = d_tidx[w];
    int cand = (lane < KT) ? d_tidx[j * KT + lane] : -1;
    unsigned f = __ballot_sync(0xffffffffu, cand == i);
    if (lane == 0) {
        atomicAdd(&d_kcnt[i], 1);
        d_kmut[w] = (f != 0);
        if (!f) atomicAdd(&d_kcnt[j], 1);
    }
}
__global__ void k_kscan() {
    __shared__ int bs[256];
    int t = threadIdx.x;
    int loc[32]; int s = 0;
#pragma unroll
    for (int q = 0; q < 32; q++) {
        loc[q] = d_kcnt[t * 32 + q];
        d_kcnt[t * 32 + q] = 0;
        s += loc[q];
    }
    bs[t] = s; __syncthreads();
    for (int off = 1; off < 256; off <<= 1) {
        int v = (t >= off) ? bs[t - off] : 0;
        __syncthreads();
        bs[t] += v;
        __syncthreads();
    }
    int run = bs[t] - s;
#pragma unroll
    for (int q = 0; q < 32; q++) {
        int i = t * 32 + q;
        d_kptr[i] = run; d_kcur[i] = run;
        run += loc[q];
    }
    if (t == 255) d_kptr[NN] = run;
}
__global__ void k_kfill() {
    int w = blockIdx.x * 256 + threadIdx.x;
    if (w >= NN * KT) return;
    int i = w / KT, j = d_tidx[w];
    float v = d_tval[w];
    int pos = atomicAdd(&d_kcur[i], 1);
    d_kidx[pos] = j; d_kval[pos] = v;
    if (!d_kmut[w]) {
        int pos2 = atomicAdd(&d_kcur[j], 1);
        d_kidx[pos2] = i; d_kval[pos2] = v;
    }
}

// -------- standalone bf16 GEMM layer 2 --------
__global__ void __launch_bounds__(256) k_gemm_bf16_l1() {
    int bn = blockIdx.x, bm = blockIdx.y;
    extern __shared__ char smem[];
    uint32_t sb = smem_u32(smem);
    gemm_body(d_h1h + (size_t)bm * 128 * 256, d_h1l + (size_t)bm * 128 * 256,
              d_w2h + (size_t)bn * 128 * 256, d_w2l + (size_t)bn * 128 * 256,
              d_hw, (size_t)bm * 128, bn * 128, smem, sb, threadIdx.x);
}

// -------- gather-based A_tot @ X --------
template <int L>
__global__ void k_spmm_gather(const float* __restrict__ alphap) {
    int gw = (blockIdx.x * 256 + threadIdx.x) >> 5, lane = threadIdx.x & 31;
    if (gw >= NN) return;
    const float* X = (L == 0) ? d_xw : d_hw;
    float* out = (L == 0) ? d_h1 : d_emb;
    float alpha = *alphap;
    float di = d_dinv[gw];
    const float4* xr = (const float4*)(X + (size_t)gw * 256);
    float4 x0 = xr[lane], x1 = xr[lane + 32];
    float sc = di * di;
    float4 a0 = make_float4(sc*x0.x, sc*x0.y, sc*x0.z, sc*x0.w);
    float4 a1 = make_float4(sc*x1.x, sc*x1.y, sc*x1.z, sc*x1.w);
    int b = d_rptr[gw], e = d_rptr[gw + 1];
    int p = b;
    for (; p + 1 < e; p += 2) {
        float w0 = d_cw[p], w1 = d_cw[p + 1];
        const float4* s0 = (const float4*)(X + (size_t)d_csrc[p] * 256);
        const float4* s1 = (const float4*)(X + (size_t)d_csrc[p + 1] * 256);
        float4 v00 = s0[lane], v01 = s0[lane + 32];
        float4 v10 = s1[lane], v11 = s1[lane + 32];
        fma4(a0, w0, v00); fma4(a1, w0, v01);
        fma4(a0, w1, v10); fma4(a1, w1, v11);
    }
    if (p < e) {
        float wv = d_cw[p];
        const float4* xs = (const float4*)(X + (size_t)d_csrc[p] * 256);
        fma4(a0, wv, xs[lane]); fma4(a1, wv, xs[lane + 32]);
    }
    a0.x*=alpha; a0.y*=alpha; a0.z*=alpha; a0.w*=alpha;
    a1.x*=alpha; a1.y*=alpha; a1.z*=alpha; a1.w*=alpha;
    int kb = d_kptr[gw], ke = d_kptr[gw + 1];
    p = kb;
    for (; p + 1 < ke; p += 2) {
        float w0 = d_kval[p], w1 = d_kval[p + 1];
        const float4* s0 = (const float4*)(X + (size_t)d_kidx[p] * 256);
        const float4* s1 = (const float4*)(X + (size_t)d_kidx[p + 1] * 256);
        float4 v00 = s0[lane], v01 = s0[lane + 32];
        float4 v10 = s1[lane], v11 = s1[lane + 32];
        fma4(a0, w0, v00); fma4(a1, w0, v01);
        fma4(a0, w1, v10); fma4(a1, w1, v11);
    }
    if (p < ke) {
        float v = d_kval[p];
        const float4* xs = (const float4*)(X + (size_t)d_kidx[p] * 256);
        fma4(a0, v, xs[lane]); fma4(a1, v, xs[lane + 32]);
    }
    if (L == 0) {
        a0.x=fmaxf(a0.x,0.f); a0.y=fmaxf(a0.y,0.f); a0.z=fmaxf(a0.z,0.f); a0.w=fmaxf(a0.w,0.f);
        a1.x=fmaxf(a1.x,0.f); a1.y=fmaxf(a1.y,0.f); a1.z=fmaxf(a1.z,0.f); a1.w=fmaxf(a1.w,0.f);
        uint2* h1h = (uint2*)(d_h1h + (size_t)gw * 256);
        uint2* h1l = (uint2*)(d_h1l + (size_t)gw * 256);
        uint2 p0 = pack_bf16x4(a0);
        uint2 p1 = pack_bf16x4(a1);
        h1h[lane] = p0; h1h[lane + 32] = p1;
        __nv_bfloat162* pv0 = (__nv_bfloat162*)&p0;
        __nv_bfloat162* pv1 = (__nv_bfloat162*)&p1;
        float4 r0 = make_float4(a0.x - __bfloat162float(__low2bfloat16(pv0[0])),
                                a0.y - __bfloat162float(__high2bfloat16(pv0[0])),
                                a0.z - __bfloat162float(__low2bfloat16(pv0[1])),
                                a0.w - __bfloat162float(__high2bfloat16(pv0[1])));
        float4 r1 = make_float4(a1.x - __bfloat162float(__low2bfloat16(pv1[0])),
                                a1.y - __bfloat162float(__high2bfloat16(pv1[0])),
                                a1.z - __bfloat162float(__low2bfloat16(pv1[1])),
                                a1.w - __bfloat162float(__high2bfloat16(pv1[1])));
        h1l[lane] = pack_bf16x4(r0); h1l[lane + 32] = pack_bf16x4(r1);
    }
    float4* orow = (float4*)(out + (size_t)gw * 256);
    orow[lane] = a0; orow[lane + 32] = a1;
}

// -------- classification --------
__global__ void k_cls_scatter(const int* __restrict__ labels, const int* __restrict__ nidx) {
    int w = (blockIdx.x*256+threadIdx.x) >> 5, lane = threadIdx.x & 31;
    if (w >= NSEL) return;
    int lbl = labels[w];
    const float4* er = (const float4*)(d_emb + (size_t)nidx[w]*HIDD);
    float4* sr = (float4*)(d_sums + lbl*HIDD);
#pragma unroll
    for (int q = 0; q < 2; q++) {
        int f = lane + 32*q; float4 v = er[f];
        red4(&sr[f], v.x, v.y, v.z, v.w);
    }
    if (lane == 0) atomicAdd(&d_cnt[lbl], 1.f);
}
__global__ void k_proto() {
    int c = blockIdx.x, t = threadIdx.x;
    float cnt = d_cnt[c];
    float sm = d_sums[c*HIDD+t];
    float p = sm / fmaxf(cnt, 1.f);
    __shared__ float red[256];
    red[t] = p*p;
    __syncthreads();
    for (int s = 128; s > 0; s >>= 1) { if (t < s) red[t] += red[t+s]; __syncthreads(); }
    d_pn[c*HIDD+t] = p / (sqrtf(red[0]) + EPSF);
    d_sums[c*HIDD+t] = 0.f;
    if (t == 0) d_cnt[c] = 0.f;
}
__global__ void k_out(const int* __restrict__ nidx, float* __restrict__ out) {
    int w = (blockIdx.x*256+threadIdx.x) >> 5, lane = threadIdx.x & 31;
    if (w >= NSEL) return;
    const float* er = d_emb + (size_t)nidx[w]*HIDD;
    float v[8]; float ss = 0.f;
#pragma unroll
    for (int q = 0; q < 8; q++) { v[q] = er[lane+32*q]; ss += v[q]*v[q]; }
    ss = warp_sum(ss);
    float rn = 1.f / (sqrtf(ss) + EPSF);
#pragma unroll
    for (int c = 0; c < NCLS; c++) {
        float dp = 0.f;
#pragma unroll
        for (int q = 0; q < 8; q++) dp += v[q] * d_pn[c*HIDD + lane + 32*q];
        dp = warp_sum(dp);
        if (lane == 0) out[w*NCLS + c] = dp * rn * 5.0f;
    }
}

extern "C" void kernel_launch(void* const* d_in, const int* in_sizes, int n_in,
                              void* d_out, int out_size) {
    const float* x   = (const float*)d_in[0];
    const float* cw  = (const float*)d_in[1];
    const float* alp = (const float*)d_in[2];
    const float* ps  = (const float*)d_in[3];
    const float* st  = (const float*)d_in[4];
    const float* bal = (const float*)d_in[5];
    const float* W1  = (const float*)d_in[6];
    const float* W2  = (const float*)d_in[7];
    const int*   ei  = (const int*)d_in[8];
    const int*   lab = (const int*)d_in[9];
    const int*   nix = (const int*)d_in[10];
    float* out = (float*)d_out;
    const int* esrc = ei;
    const int* edst = ei + NE;

    cudaFuncSetAttribute(k_sims_gemm0, cudaFuncAttributeMaxDynamicSharedMemorySize, SIMS_SMEM);
    cudaFuncSetAttribute(k_gemm_bf16_l1, cudaFuncAttributeMaxDynamicSharedMemorySize, SIMS_SMEM);

    k_fea<<<NN*FIN/256, 256>>>(x, cw, ps, st, edst, W1, W2);
    k_scan<<<1, 256>>>();
    k_fill<<<NE/256, 256>>>(esrc, edst);
    k_agg_h<<<NN/8, 256>>>(bal);
    k_sims_gemm0<<<NGEMM0 + NTILES, 256, SIMS_SMEM>>>();
    k_topk<<<NN, 256>>>(alp);
    k_kcount<<<NN*KT/8, 256>>>();
    k_kscan<<<1, 256>>>();
    k_kfill<<<(NN*KT+255)/256, 256>>>();

    k_spmm_gather<0><<<NN/8, 256>>>(alp);
    k_gemm_bf16_l1<<<dim3(2, 64), 256, SIMS_SMEM>>>();
    k_spmm_gather<1><<<NN/8, 256>>>(alp);

    k_cls_scatter<<<NSEL/8, 256>>>(lab, nix);
    k_proto<<<NCLS, 256>>>();
    k_out<<<NSEL/8, 256>>>(nix, out);
}

// round 15
// speedup vs baseline: 1.0863x; 1.0630x over previous
#include <cuda_runtime.h>
#include <cuda_bf16.h>
#include <math.h>
#include <float.h>
#include <stdint.h>

#define NN   8192
#define FIN  256
#define HIDD 256
#define NE   131072
#define KT   17
#define CAP  96
#define CANDCAP 96
#define NCLS 10
#define NSEL 4096
#define EPSF 1e-8f
#define NGEMM0 128
#define NTILES 2080

__device__ __align__(16) float d_fea[NN * FIN];
__device__ __align__(16) __nv_bfloat16 d_feah[NN * FIN];
__device__ __align__(16) __nv_bfloat16 d_feal[NN * FIN];
__device__ int   d_cnt_e[NN];          // degree; self-clean in k_cls_scatter
__device__ int   d_cur[NN];            // bin cursor; self-clean in k_agg_h
__device__ int   d_csrc[NN * CAP];
__device__ float d_cw[NN * CAP];
__device__ __align__(16) float d_hn[NN * 512];
__device__ __align__(16) __nv_bfloat16 d_hb[NN * 512];
__device__ __nv_bfloat16 d_simh[(size_t)NN * NN];
__device__ int   d_tidx[NN * KT];
__device__ float d_tval[NN * KT];
__device__ int   d_kcnt[NN];           // self-clean in k_kscan
__device__ int   d_kptr[NN + 1];
__device__ int   d_kcur[NN];
__device__ unsigned char d_kmut[NN * KT];
__device__ int   d_kidx[NN * KT * 2];
__device__ float d_kval[NN * KT * 2];
__device__ __align__(16) __nv_bfloat16 d_w1h[FIN * HIDD];
__device__ __align__(16) __nv_bfloat16 d_w1l[FIN * HIDD];
__device__ __align__(16) __nv_bfloat16 d_w2h[HIDD * HIDD];
__device__ __align__(16) __nv_bfloat16 d_w2l[HIDD * HIDD];
__device__ __align__(16) float d_xw[NN * HIDD];
__device__ __align__(16) float d_h1[NN * HIDD];
__device__ __align__(16) __nv_bfloat16 d_h1h[NN * HIDD];
__device__ __align__(16) __nv_bfloat16 d_h1l[NN * HIDD];
__device__ __align__(16) float d_hw[NN * HIDD];
__device__ __align__(16) float d_emb[NN * HIDD];
__device__ __align__(16) float d_sums[NCLS * HIDD]; // self-clean in k_proto
__device__ float d_cnt[NCLS];                       // self-clean in k_proto
__device__ float d_pn[NCLS * HIDD];

__device__ __forceinline__ float warp_sum(float v) {
#pragma unroll
    for (int o = 16; o > 0; o >>= 1) v += __shfl_xor_sync(0xffffffffu, v, o);
    return v;
}
__device__ __forceinline__ void red4(float4* addr, float a, float b, float c, float d) {
    asm volatile("red.global.add.v4.f32 [%0], {%1,%2,%3,%4};"
                 :: "l"(addr), "f"(a), "f"(b), "f"(c), "f"(d) : "memory");
}
__device__ __forceinline__ void fma4(float4& a, float w, const float4 v) {
    a.x += w * v.x; a.y += w * v.y; a.z += w * v.z; a.w += w * v.w;
}
__device__ __forceinline__ uint2 pack_bf16x4(float4 v) {
    __nv_bfloat162 lo = __floats2bfloat162_rn(v.x, v.y);
    __nv_bfloat162 hi = __floats2bfloat162_rn(v.z, v.w);
    uint2 r;
    r.x = *reinterpret_cast<uint32_t*>(&lo);
    r.y = *reinterpret_cast<uint32_t*>(&hi);
    return r;
}
__device__ __forceinline__ uint32_t bf16key(uint32_t b) {
    return (b & 0x8000u) ? (~b & 0xFFFFu) : (b | 0x8000u);
}

// -------- launch 1: fea = elu(...) + hi/lo split + degree count + wpack --------
__global__ void k_fea(const float* __restrict__ x, const float* __restrict__ cw,
                      const float* __restrict__ ps, const float* __restrict__ st,
                      const int* __restrict__ dst,
                      const float* __restrict__ W1, const float* __restrict__ W2) {
    int idx = blockIdx.x * 256 + threadIdx.x;
    int f = idx & (FIN - 1);
    float z = x[idx] * (cw[0] * ps[f] + cw[1] * st[f]);
    float r = z > 0.f ? z : expm1f(z);
    d_fea[idx] = r;
    __nv_bfloat16 hi = __float2bfloat16(r);
    d_feah[idx] = hi;
    d_feal[idx] = __float2bfloat16(r - __bfloat162float(hi));
    if (idx < NE) {
        atomicAdd(&d_cnt_e[dst[idx]], 1);
        int wsel = idx >> 16;
        int e = idx & 0xFFFF;
        int k = e >> 8, n = e & 255;
        float v = (wsel ? W2 : W1)[e];
        __nv_bfloat16 wh = __float2bfloat16(v);
        (wsel ? d_w2h : d_w1h)[n * 256 + k] = wh;
        (wsel ? d_w2l : d_w1l)[n * 256 + k] = __float2bfloat16(v - __bfloat162float(wh));
    }
}
// -------- launch 2: direct-slot bin-CSR fill --------
__global__ void k_bin(const int* __restrict__ src, const int* __restrict__ dst) {
    int e = blockIdx.x * 256 + threadIdx.x;
    if (e >= NE) return;
    int s = src[e], d = dst[e];
    int pos = atomicAdd(&d_cur[d], 1);
    if (pos < CAP) {
        d_csrc[d * CAP + pos] = s;
        d_cw[d * CAP + pos] = rsqrtf((float)(d_cnt_e[s] + 1)) * rsqrtf((float)(d_cnt_e[d] + 1));
    }
}
// -------- launch 3: fused aggregate-gather + h-normalize + bf16 --------
__global__ void k_agg_h(const float* __restrict__ bal) {
    int gw = (blockIdx.x * 256 + threadIdx.x) >> 5, lane = threadIdx.x & 31;
    if (gw >= NN) return;
    int deg = d_cnt_e[gw];
    if (lane == 0) d_cur[gw] = 0;                 // self-clean
    float di = rsqrtf((float)(deg + 1));
    const float4* fr = (const float4*)(d_fea + (size_t)gw * 256);
    float4 f0 = fr[lane], f1 = fr[lane + 32];
    float sc = di * di;
    float4 a0 = make_float4(sc*f0.x, sc*f0.y, sc*f0.z, sc*f0.w);
    float4 a1 = make_float4(sc*f1.x, sc*f1.y, sc*f1.z, sc*f1.w);
    int b = gw * CAP, e = b + min(deg, CAP);
    int p = b;
    for (; p + 1 < e; p += 2) {
        float w0 = d_cw[p], w1 = d_cw[p + 1];
        const float4* s0 = (const float4*)(d_fea + (size_t)d_csrc[p] * 256);
        const float4* s1 = (const float4*)(d_fea + (size_t)d_csrc[p + 1] * 256);
        float4 v00 = s0[lane], v01 = s0[lane + 32];
        float4 v10 = s1[lane], v11 = s1[lane + 32];
        fma4(a0, w0, v00); fma4(a1, w0, v01);
        fma4(a0, w1, v10); fma4(a1, w1, v11);
    }
    if (p < e) {
        float wv = d_cw[p];
        const float4* fs = (const float4*)(d_fea + (size_t)d_csrc[p] * 256);
        fma4(a0, wv, fs[lane]); fma4(a1, wv, fs[lane + 32]);
    }
    const float4* bb = (const float4*)bal;
    float4 bA = bb[lane], bB = bb[lane + 32], bC = bb[64 + lane], bD = bb[96 + lane];
    float4 hA = make_float4(f0.x*bA.x, f0.y*bA.y, f0.z*bA.z, f0.w*bA.w);
    float4 hB = make_float4(f1.x*bB.x, f1.y*bB.y, f1.z*bB.z, f1.w*bB.w);
    float4 hC = make_float4(a0.x*bC.x, a0.y*bC.y, a0.z*bC.z, a0.w*bC.w);
    float4 hD = make_float4(a1.x*bD.x, a1.y*bD.y, a1.z*bD.z, a1.w*bD.w);
    float ss = hA.x*hA.x+hA.y*hA.y+hA.z*hA.z+hA.w*hA.w
             + hB.x*hB.x+hB.y*hB.y+hB.z*hB.z+hB.w*hB.w
             + hC.x*hC.x+hC.y*hC.y+hC.z*hC.z+hC.w*hC.w
             + hD.x*hD.x+hD.y*hD.y+hD.z*hD.z+hD.w*hD.w;
    ss = warp_sum(ss);
    float rn = 1.f / (sqrtf(ss) + EPSF);
    hA.x*=rn; hA.y*=rn; hA.z*=rn; hA.w*=rn;
    hB.x*=rn; hB.y*=rn; hB.z*=rn; hB.w*=rn;
    hC.x*=rn; hC.y*=rn; hC.z*=rn; hC.w*=rn;
    hD.x*=rn; hD.y*=rn; hD.z*=rn; hD.w*=rn;
    float4* hr = (float4*)(d_hn + (size_t)gw * 512);
    hr[lane] = hA; hr[lane + 32] = hB; hr[64 + lane] = hC; hr[96 + lane] = hD;
    uint2* hb = (uint2*)(d_hb + (size_t)gw * 512);
    hb[lane] = pack_bf16x4(hA); hb[lane + 32] = pack_bf16x4(hB);
    hb[64 + lane] = pack_bf16x4(hC); hb[96 + lane] = pack_bf16x4(hD);
}

// ======== mma helpers ========
__device__ __forceinline__ uint32_t smem_u32(const void* p) {
    uint32_t a;
    asm("{ .reg .u64 t; cvta.to.shared.u64 t, %1; cvt.u32.u64 %0, t; }" : "=r"(a) : "l"(p));
    return a;
}
__device__ __forceinline__ void ldsm4(uint32_t* r, uint32_t addr) {
    asm volatile("ldmatrix.sync.aligned.m8n8.x4.shared.b16 {%0,%1,%2,%3}, [%4];"
                 : "=r"(r[0]), "=r"(r[1]), "=r"(r[2]), "=r"(r[3]) : "r"(addr));
}
__device__ __forceinline__ void mma16816(float* c, const uint32_t* a, uint32_t b0, uint32_t b1) {
    asm volatile("mma.sync.aligned.m16n8k16.row.col.f32.bf16.bf16.f32 "
                 "{%0,%1,%2,%3}, {%4,%5,%6,%7}, {%8,%9}, {%0,%1,%2,%3};"
                 : "+f"(c[0]), "+f"(c[1]), "+f"(c[2]), "+f"(c[3])
                 : "r"(a[0]), "r"(a[1]), "r"(a[2]), "r"(a[3]), "r"(b0), "r"(b1));
}
__device__ __forceinline__ void sims_load(uint32_t sbase, const __nv_bfloat16* Ag,
                                          const __nv_bfloat16* Bg, int c, int tid) {
#pragma unroll
    for (int h = 0; h < 2; h++) {
        const __nv_bfloat16* G = h ? Bg : Ag;
        uint32_t base = sbase + (uint32_t)h * 16384;
#pragma unroll
        for (int q = 0; q < 4; q++) {
            int seg = tid + 256 * q;
            int r = seg >> 3, s8 = seg & 7;
            uint32_t dst = base + r * 128 + ((s8 ^ (r & 7)) << 4);
            const char* src = (const char*)(G + (size_t)r * 512 + c * 64 + s8 * 8);
            asm volatile("cp.async.cg.shared.global [%0], [%1], 16;"
                         :: "r"(dst), "l"(src) : "memory");
        }
    }
    asm volatile("cp.async.commit_group;" ::: "memory");
}
__device__ __forceinline__ void gload(uint32_t dst_base, const __nv_bfloat16* G,
                                      int k0, int tid) {
#pragma unroll
    for (int q = 0; q < 4; q++) {
        int seg = tid + 256 * q;
        int r = seg >> 3, s8 = seg & 7;
        uint32_t dst = dst_base + r * 128 + ((s8 ^ (r & 7)) << 4);
        const char* src = (const char*)(G + (size_t)r * 256 + k0 + s8 * 8);
        asm volatile("cp.async.cg.shared.global [%0], [%1], 16;"
                     :: "r"(dst), "l"(src) : "memory");
    }
}
#define SIMS_SMEM 66048

// -------- shared gemm body: C[128x256 tile] = A @ W (3-term hi/lo bf16) --------
__device__ __forceinline__ void gemm_body(const __nv_bfloat16* Ah, const __nv_bfloat16* Al,
                                          const __nv_bfloat16* Bh, const __nv_bfloat16* Bl,
                                          float* C, size_t gm0, int nc0,
                                          char* smem, uint32_t sb, int tid) {
    int lane = tid & 31, w = tid >> 5;
    int wm = (w & 1) * 64, wn = (w >> 1) * 32;
    float acc[4][4][4];
#pragma unroll
    for (int mt = 0; mt < 4; mt++)
#pragma unroll
        for (int nt = 0; nt < 4; nt++)
#pragma unroll
            for (int e = 0; e < 4; e++) acc[mt][nt][e] = 0.f;
    int lr = lane & 15, lks = lane >> 4;
    for (int c = 0; c < 4; c++) {
        int k0 = c * 64;
        gload(sb,         Ah, k0, tid);
        gload(sb + 16384, Al, k0, tid);
        gload(sb + 32768, Bh, k0, tid);
        gload(sb + 49152, Bl, k0, tid);
        asm volatile("cp.async.commit_group;" ::: "memory");
        asm volatile("cp.async.wait_group 0;" ::: "memory");
        __syncthreads();
#pragma unroll
        for (int ks = 0; ks < 4; ks++) {
            int segk = ks * 2 + lks;
            uint32_t a[4][4], bh[2][4], bl[2][4];
#pragma unroll
            for (int bt = 0; bt < 2; bt++) {
                int r = wn + bt * 16 + lr;
                uint32_t off = r * 128 + ((segk ^ (r & 7)) << 4);
                ldsm4(bh[bt], sb + 32768 + off);
                ldsm4(bl[bt], sb + 49152 + off);
            }
#pragma unroll
            for (int mt = 0; mt < 4; mt++) {
                int r = wm + mt * 16 + lr;
                ldsm4(a[mt], sb + r * 128 + ((segk ^ (r & 7)) << 4));
            }
#pragma unroll
            for (int mt = 0; mt < 4; mt++)
#pragma unroll
                for (int nt = 0; nt < 4; nt++) {
                    mma16816(acc[mt][nt], a[mt], bh[nt >> 1][nt & 1], bh[nt >> 1][(nt & 1) + 2]);
                    mma16816(acc[mt][nt], a[mt], bl[nt >> 1][nt & 1], bl[nt >> 1][(nt & 1) + 2]);
                }
#pragma unroll
            for (int mt = 0; mt < 4; mt++) {
                int r = wm + mt * 16 + lr;
                ldsm4(a[mt], sb + 16384 + r * 128 + ((segk ^ (r & 7)) << 4));
            }
#pragma unroll
            for (int mt = 0; mt < 4; mt++)
#pragma unroll
                for (int nt = 0; nt < 4; nt++)
                    mma16816(acc[mt][nt], a[mt], bh[nt >> 1][nt & 1], bh[nt >> 1][(nt & 1) + 2]);
        }
        __syncthreads();
    }
    float* sf = (float*)smem;
    int g = lane >> 2, tq = lane & 3;
#pragma unroll
    for (int mt = 0; mt < 4; mt++)
#pragma unroll
        for (int nt = 0; nt < 4; nt++) {
            int r0 = wm + mt * 16 + g, c0 = wn + nt * 8 + tq * 2;
            sf[r0 * 129 + c0]           = acc[mt][nt][0];
            sf[r0 * 129 + c0 + 1]       = acc[mt][nt][1];
            sf[(r0 + 8) * 129 + c0]     = acc[mt][nt][2];
            sf[(r0 + 8) * 129 + c0 + 1] = acc[mt][nt][3];
        }
    __syncthreads();
    for (int it = tid; it < 128 * 128; it += 256) {
        int r = it >> 7, col = it & 127;
        C[(gm0 + r) * 256 + nc0 + col] = sf[r * 129 + col];
    }
}

// ======== launch 4 (profiled): gemm<0> blocks + sims upper-tri tiles ========
__global__ void __launch_bounds__(256, 2) k_sims_gemm0() {
    int bidx = blockIdx.x;
    extern __shared__ char smem[];
    uint32_t sb = smem_u32(smem);
    int tid = threadIdx.x;
    if (bidx < NGEMM0) {
        int g = bidx;
        int bn = g & 1, bm = g >> 1;
        gemm_body(d_feah + (size_t)bm * 128 * 256, d_feal + (size_t)bm * 128 * 256,
                  d_w1h + (size_t)bn * 128 * 256, d_w1l + (size_t)bn * 128 * 256,
                  d_xw, (size_t)bm * 128, bn * 128, smem, sb, tid);
        return;
    }
    int idx = bidx - NGEMM0;
    int bj = (int)((sqrtf(8.f * idx + 1.f) - 1.f) * 0.5f);
    while ((bj + 1) * (bj + 2) / 2 <= idx) bj++;
    while (bj * (bj + 1) / 2 > idx) bj--;
    int bi = idx - bj * (bj + 1) / 2;           // bi <= bj
    int lane = tid & 31, w = tid >> 5;
    int wm = (w & 1) * 64, wn = (w >> 1) * 32;

    const __nv_bfloat16* Ag = d_hb + (size_t)bi * 128 * 512;
    const __nv_bfloat16* Bg = d_hb + (size_t)bj * 128 * 512;

    float acc[4][4][4];
#pragma unroll
    for (int mt = 0; mt < 4; mt++)
#pragma unroll
        for (int nt = 0; nt < 4; nt++)
#pragma unroll
            for (int e = 0; e < 4; e++) acc[mt][nt][e] = 0.f;

    sims_load(sb, Ag, Bg, 0, tid);
    int lr = lane & 15, lks = lane >> 4;
    for (int c = 0; c < 8; c++) {
        if (c < 7) sims_load(sb + ((c + 1) & 1) * 32768, Ag, Bg, c + 1, tid);
        if (c < 7) asm volatile("cp.async.wait_group 1;" ::: "memory");
        else       asm volatile("cp.async.wait_group 0;" ::: "memory");
        __syncthreads();
        uint32_t aB = sb + (c & 1) * 32768, bB = aB + 16384;
#pragma unroll
        for (int ks = 0; ks < 4; ks++) {
            int segk = ks * 2 + lks;
            uint32_t a[4][4], b[2][4];
#pragma unroll
            for (int mt = 0; mt < 4; mt++) {
                int r = wm + mt * 16 + lr;
                ldsm4(a[mt], aB + r * 128 + ((segk ^ (r & 7)) << 4));
            }
#pragma unroll
            for (int bt = 0; bt < 2; bt++) {
                int r = wn + bt * 16 + lr;
                ldsm4(b[bt], bB + r * 128 + ((segk ^ (r & 7)) << 4));
            }
#pragma unroll
            for (int mt = 0; mt < 4; mt++)
#pragma unroll
                for (int nt = 0; nt < 4; nt++)
                    mma16816(acc[mt][nt], a[mt], b[nt >> 1][nt & 1], b[nt >> 1][(nt & 1) + 2]);
        }
        __syncthreads();
    }
    float* sf = (float*)smem;
    int g = lane >> 2, tq = lane & 3;
#pragma unroll
    for (int mt = 0; mt < 4; mt++)
#pragma unroll
        for (int nt = 0; nt < 4; nt++) {
            int r0 = wm + mt * 16 + g, c0 = wn + nt * 8 + tq * 2;
            sf[r0 * 129 + c0]           = acc[mt][nt][0];
            sf[r0 * 129 + c0 + 1]       = acc[mt][nt][1];
            sf[(r0 + 8) * 129 + c0]     = acc[mt][nt][2];
            sf[(r0 + 8) * 129 + c0 + 1] = acc[mt][nt][3];
        }
    __syncthreads();
    size_t gi0 = (size_t)bi * 128, gj0 = (size_t)bj * 128;
    if (bi != bj) {
        for (int it = tid; it < 128 * 64; it += 256) {
            int r = it >> 6, c2 = (it & 63) * 2;
            __nv_bfloat162 p = __floats2bfloat162_rn(sf[r * 129 + c2], sf[r * 129 + c2 + 1]);
            *(__nv_bfloat162*)&d_simh[(gi0 + r) * NN + gj0 + c2] = p;
        }
        for (int it = tid; it < 128 * 64; it += 256) {
            int j = it >> 6, i2 = (it & 63) * 2;
            __nv_bfloat162 p = __floats2bfloat162_rn(sf[i2 * 129 + j], sf[(i2 + 1) * 129 + j]);
            *(__nv_bfloat162*)&d_simh[(gj0 + j) * NN + gi0 + i2] = p;
        }
    } else {
        for (int it = tid; it < 128 * 64; it += 256) {
            int r = it >> 6, c2 = (it & 63) * 2;
            float v0 = (c2 >= r)     ? sf[r * 129 + c2]     : sf[c2 * 129 + r];
            float v1 = (c2 + 1 >= r) ? sf[r * 129 + c2 + 1] : sf[(c2 + 1) * 129 + r];
            __nv_bfloat162 p = __floats2bfloat162_rn(v0, v1);
            *(__nv_bfloat162*)&d_simh[(gi0 + r) * NN + gj0 + c2] = p;
        }
    }
}

// -------- topk: max-relative bins + prefilter + exact rescore --------
__global__ void k_topk(const float* __restrict__ alphap) {
    int row = blockIdx.x, t = threadIdx.x;
    int w = t >> 5, lane = t & 31;
    const uint4* srow = (const uint4*)(d_simh + (size_t)row * NN);
    uint32_t kp[16];
#pragma unroll
    for (int q = 0; q < 4; q++) {
        uint4 r4 = srow[q * 256 + t];
        uint32_t rr[4] = {r4.x, r4.y, r4.z, r4.w};
#pragma unroll
        for (int u = 0; u < 4; u++)
            kp[q * 4 + u] = bf16key(rr[u] & 0xFFFFu) | (bf16key(rr[u] >> 16) << 16);
    }
    __shared__ int hist[256];
    __shared__ int scn[256];
    __shared__ uint32_t sMax[8];
    __shared__ int sB, cnum;
    __shared__ int   cand[CANDCAP];
    __shared__ float cex[CANDCAP];
    hist[t] = 0;
    if (t == 0) { cnum = 0; sB = 255; }
    uint32_t mk = 0;
#pragma unroll
    for (int q = 0; q < 16; q++) {
        uint32_t a = kp[q] & 0xFFFFu, b2 = kp[q] >> 16;
        mk = max(mk, max(a, b2));
    }
#pragma unroll
    for (int o = 16; o > 0; o >>= 1)
        mk = max(mk, __shfl_xor_sync(0xffffffffu, mk, o));
    if (lane == 0) sMax[w] = mk;
    __syncthreads();
    uint32_t Kmax = sMax[0];
#pragma unroll
    for (int q = 1; q < 8; q++) Kmax = max(Kmax, sMax[q]);
#pragma unroll
    for (int q = 0; q < 16; q++) {
        uint32_t d0 = (Kmax - (kp[q] & 0xFFFFu)) >> 2;
        uint32_t d1 = (Kmax - (kp[q] >> 16)) >> 2;
        if (d0 < 256) atomicAdd(&hist[d0], 1);
        if (d1 < 256) atomicAdd(&hist[d1], 1);
    }
    __syncthreads();
    int hv = hist[t];
    scn[t] = hv;
    __syncthreads();
    for (int off = 1; off < 256; off <<= 1) {
        int v = (t >= off) ? scn[t - off] : 0;
        __syncthreads();
        scn[t] += v;
        __syncthreads();
    }
    if (scn[t] >= 32 && scn[t] - hv < 32) sB = t;
    __syncthreads();
    int B = sB;
#pragma unroll
    for (int q = 0; q < 16; q++) {
        uint32_t d0 = (Kmax - (kp[q] & 0xFFFFu)) >> 2;
        uint32_t d1 = (Kmax - (kp[q] >> 16)) >> 2;
        int qq = q >> 2, u = q & 3;
        int colbase = qq * 2048 + t * 8 + u * 2;
        if ((int)d0 <= B) { int pos = atomicAdd(&cnum, 1); if (pos < CANDCAP) cand[pos] = colbase; }
        if ((int)d1 <= B) { int pos = atomicAdd(&cnum, 1); if (pos < CANDCAP) cand[pos] = colbase + 1; }
    }
    __syncthreads();
    int nc = min(cnum, CANDCAP);
    const float* hr = d_hn + (size_t)row * 512;
    for (int c = w; c < nc; c += 8) {
        const float* hj = d_hn + (size_t)cand[c] * 512;
        float s = 0.f;
#pragma unroll
        for (int e = 0; e < 16; e++) s += hr[lane + e * 32] * hj[lane + e * 32];
        s = warp_sum(s);
        if (lane == 0) cex[c] = s;
    }
    __syncthreads();
    if (t < nc) {
        float myv = cex[t]; int myi = cand[t];
        int rank = 0;
        for (int c = 0; c < nc; c++) {
            float v = cex[c]; int ci = cand[c];
            if (v > myv || (v == myv && ci < myi)) rank++;
        }
        if (rank < KT) {
            d_tidx[row * KT + rank] = myi;
            d_tval[row * KT + rank] = (1.f - *alphap) * fmaxf(myv, 0.f);
        }
    }
}

// -------- kNN symmetric CSR build (thread-per-entry) --------
__global__ void k_kcount() {
    int w = blockIdx.x * 256 + threadIdx.x;
    if (w >= NN * KT) return;
    int i = w / KT, j = d_tidx[w];
    bool found = false;
    const int* tj = d_tidx + j * KT;
#pragma unroll
    for (int q = 0; q < KT; q++) found |= (tj[q] == i);
    atomicAdd(&d_kcnt[i], 1);
    d_kmut[w] = found;
    if (!found) atomicAdd(&d_kcnt[j], 1);
}
__global__ void k_kscan() {
    __shared__ int bs[256];
    int t = threadIdx.x;
    int loc[32]; int s = 0;
#pragma unroll
    for (int q = 0; q < 32; q++) {
        loc[q] = d_kcnt[t * 32 + q];
        d_kcnt[t * 32 + q] = 0;
        s += loc[q];
    }
    bs[t] = s; __syncthreads();
    for (int off = 1; off < 256; off <<= 1) {
        int v = (t >= off) ? bs[t - off] : 0;
        __syncthreads();
        bs[t] += v;
        __syncthreads();
    }
    int run = bs[t] - s;
#pragma unroll
    for (int q = 0; q < 32; q++) {
        int i = t * 32 + q;
        d_kptr[i] = run; d_kcur[i] = run;
        run += loc[q];
    }
    if (t == 255) d_kptr[NN] = run;
}
__global__ void k_kfill() {
    int w = blockIdx.x * 256 + threadIdx.x;
    if (w >= NN * KT) return;
    int i = w / KT, j = d_tidx[w];
    float v = d_tval[w];
    int pos = atomicAdd(&d_kcur[i], 1);
    d_kidx[pos] = j; d_kval[pos] = v;
    if (!d_kmut[w]) {
        int pos2 = atomicAdd(&d_kcur[j], 1);
        d_kidx[pos2] = i; d_kval[pos2] = v;
    }
}

// -------- standalone bf16 GEMM layer 2 --------
__global__ void __launch_bounds__(256) k_gemm_bf16_l1() {
    int bn = blockIdx.x, bm = blockIdx.y;
    extern __shared__ char smem[];
    uint32_t sb = smem_u32(smem);
    gemm_body(d_h1h + (size_t)bm * 128 * 256, d_h1l + (size_t)bm * 128 * 256,
              d_w2h + (size_t)bn * 128 * 256, d_w2l + (size_t)bn * 128 * 256,
              d_hw, (size_t)bm * 128, bn * 128, smem, sb, threadIdx.x);
}

// -------- gather-based A_tot @ X --------
template <int L>
__global__ void k_spmm_gather(const float* __restrict__ alphap) {
    int gw = (blockIdx.x * 256 + threadIdx.x) >> 5, lane = threadIdx.x & 31;
    if (gw >= NN) return;
    const float* X = (L == 0) ? d_xw : d_hw;
    float* out = (L == 0) ? d_h1 : d_emb;
    float alpha = *alphap;
    int deg = d_cnt_e[gw];
    float di = rsqrtf((float)(deg + 1));
    const float4* xr = (const float4*)(X + (size_t)gw * 256);
    float4 x0 = xr[lane], x1 = xr[lane + 32];
    float sc = di * di;
    float4 a0 = make_float4(sc*x0.x, sc*x0.y, sc*x0.z, sc*x0.w);
    float4 a1 = make_float4(sc*x1.x, sc*x1.y, sc*x1.z, sc*x1.w);
    int b = gw * CAP, e = b + min(deg, CAP);
    int p = b;
    for (; p + 1 < e; p += 2) {
        float w0 = d_cw[p], w1 = d_cw[p + 1];
        const float4* s0 = (const float4*)(X + (size_t)d_csrc[p] * 256);
        const float4* s1 = (const float4*)(X + (size_t)d_csrc[p + 1] * 256);
        float4 v00 = s0[lane], v01 = s0[lane + 32];
        float4 v10 = s1[lane], v11 = s1[lane + 32];
        fma4(a0, w0, v00); fma4(a1, w0, v01);
        fma4(a0, w1, v10); fma4(a1, w1, v11);
    }
    if (p < e) {
        float wv = d_cw[p];
        const float4* xs = (const float4*)(X + (size_t)d_csrc[p] * 256);
        fma4(a0, wv, xs[lane]); fma4(a1, wv, xs[lane + 32]);
    }
    a0.x*=alpha; a0.y*=alpha; a0.z*=alpha; a0.w*=alpha;
    a1.x*=alpha; a1.y*=alpha; a1.z*=alpha; a1.w*=alpha;
    int kb = d_kptr[gw], ke = d_kptr[gw + 1];
    p = kb;
    for (; p + 1 < ke; p += 2) {
        float w0 = d_kval[p], w1 = d_kval[p + 1];
        const float4* s0 = (const float4*)(X + (size_t)d_kidx[p] * 256);
        const float4* s1 = (const float4*)(X + (size_t)d_kidx[p + 1] * 256);
        float4 v00 = s0[lane], v01 = s0[lane + 32];
        float4 v10 = s1[lane], v11 = s1[lane + 32];
        fma4(a0, w0, v00); fma4(a1, w0, v01);
        fma4(a0, w1, v10); fma4(a1, w1, v11);
    }
    if (p < ke) {
        float v = d_kval[p];
        const float4* xs = (const float4*)(X + (size_t)d_kidx[p] * 256);
        fma4(a0, v, xs[lane]); fma4(a1, v, xs[lane + 32]);
    }
    if (L == 0) {
        a0.x=fmaxf(a0.x,0.f); a0.y=fmaxf(a0.y,0.f); a0.z=fmaxf(a0.z,0.f); a0.w=fmaxf(a0.w,0.f);
        a1.x=fmaxf(a1.x,0.f); a1.y=fmaxf(a1.y,0.f); a1.z=fmaxf(a1.z,0.f); a1.w=fmaxf(a1.w,0.f);
        uint2* h1h = (uint2*)(d_h1h + (size_t)gw * 256);
        uint2* h1l = (uint2*)(d_h1l + (size_t)gw * 256);
        uint2 p0 = pack_bf16x4(a0);
        uint2 p1 = pack_bf16x4(a1);
        h1h[lane] = p0; h1h[lane + 32] = p1;
        __nv_bfloat162* pv0 = (__nv_bfloat162*)&p0;
        __nv_bfloat162* pv1 = (__nv_bfloat162*)&p1;
        float4 r0 = make_float4(a0.x - __bfloat162float(__low2bfloat16(pv0[0])),
                                a0.y - __bfloat162float(__high2bfloat16(pv0[0])),
                                a0.z - __bfloat162float(__low2bfloat16(pv0[1])),
                                a0.w - __bfloat162float(__high2bfloat16(pv0[1])));
        float4 r1 = make_float4(a1.x - __bfloat162float(__low2bfloat16(pv1[0])),
                                a1.y - __bfloat162float(__high2bfloat16(pv1[0])),
                                a1.z - __bfloat162float(__low2bfloat16(pv1[1])),
                                a1.w - __bfloat162float(__high2bfloat16(pv1[1])));
        h1l[lane] = pack_bf16x4(r0); h1l[lane + 32] = pack_bf16x4(r1);
    }
    float4* orow = (float4*)(out + (size_t)gw * 256);
    orow[lane] = a0; orow[lane + 32] = a1;
}

// -------- classification --------
__global__ void k_cls_scatter(const int* __restrict__ labels, const int* __restrict__ nidx) {
    int idx = blockIdx.x * 256 + threadIdx.x;
    if (idx < NN) d_cnt_e[idx] = 0;              // self-clean degree counts
    int w = idx >> 5, lane = idx & 31;
    if (w >= NSEL) return;
    int lbl = labels[w];
    const float4* er = (const float4*)(d_emb + (size_t)nidx[w]*HIDD);
    float4* sr = (float4*)(d_sums + lbl*HIDD);
#pragma unroll
    for (int q = 0; q < 2; q++) {
        int f = lane + 32*q; float4 v = er[f];
        red4(&sr[f], v.x, v.y, v.z, v.w);
    }
    if (lane == 0) atomicAdd(&d_cnt[lbl], 1.f);
}
__global__ void k_proto() {
    int c = blockIdx.x, t = threadIdx.x;
    float cnt = d_cnt[c];
    float sm = d_sums[c*HIDD+t];
    float p = sm / fmaxf(cnt, 1.f);
    __shared__ float red[256];
    red[t] = p*p;
    __syncthreads();
    for (int s = 128; s > 0; s >>= 1) { if (t < s) red[t] += red[t+s]; __syncthreads(); }
    d_pn[c*HIDD+t] = p / (sqrtf(red[0]) + EPSF);
    d_sums[c*HIDD+t] = 0.f;
    if (t == 0) d_cnt[c] = 0.f;
}
__global__ void k_out(const int* __restrict__ nidx, float* __restrict__ out) {
    int w = (blockIdx.x*256+threadIdx.x) >> 5, lane = threadIdx.x & 31;
    if (w >= NSEL) return;
    const float* er = d_emb + (size_t)nidx[w]*HIDD;
    float v[8]; float ss = 0.f;
#pragma unroll
    for (int q = 0; q < 8; q++) { v[q] = er[lane+32*q]; ss += v[q]*v[q]; }
    ss = warp_sum(ss);
    float rn = 1.f / (sqrtf(ss) + EPSF);
#pragma unroll
    for (int c = 0; c < NCLS; c++) {
        float dp = 0.f;
#pragma unroll
        for (int q = 0; q < 8; q++) dp += v[q] * d_pn[c*HIDD + lane + 32*q];
        dp = warp_sum(dp);
        if (lane == 0) out[w*NCLS + c] = dp * rn * 5.0f;
    }
}

extern "C" void kernel_launch(void* const* d_in, const int* in_sizes, int n_in,
                              void* d_out, int out_size) {
    const float* x   = (const float*)d_in[0];
    const float* cw  = (const float*)d_in[1];
    const float* alp = (const float*)d_in[2];
    const float* ps  = (const float*)d_in[3];
    const float* st  = (const float*)d_in[4];
    const float* bal = (const float*)d_in[5];
    const float* W1  = (const float*)d_in[6];
    const float* W2  = (const float*)d_in[7];
    const int*   ei  = (const int*)d_in[8];
    const int*   lab = (const int*)d_in[9];
    const int*   nix = (const int*)d_in[10];
    float* out = (float*)d_out;
    const int* esrc = ei;
    const int* edst = ei + NE;

    cudaFuncSetAttribute(k_sims_gemm0, cudaFuncAttributeMaxDynamicSharedMemorySize, SIMS_SMEM);
    cudaFuncSetAttribute(k_gemm_bf16_l1, cudaFuncAttributeMaxDynamicSharedMemorySize, SIMS_SMEM);

    k_fea<<<NN*FIN/256, 256>>>(x, cw, ps, st, edst, W1, W2);     // 1
    k_bin<<<NE/256, 256>>>(esrc, edst);                          // 2
    k_agg_h<<<NN/8, 256>>>(bal);                                 // 3
    k_sims_gemm0<<<NGEMM0 + NTILES, 256, SIMS_SMEM>>>();         // 4 <- ncu
    k_topk<<<NN, 256>>>(alp);
    k_kcount<<<(NN*KT+255)/256, 256>>>();
    k_kscan<<<1, 256>>>();
    k_kfill<<<(NN*KT+255)/256, 256>>>();

    k_spmm_gather<0><<<NN/8, 256>>>(alp);
    k_gemm_bf16_l1<<<dim3(2, 64), 256, SIMS_SMEM>>>();
    k_spmm_gather<1><<<NN/8, 256>>>(alp);

    k_cls_scatter<<<NSEL/8, 256>>>(lab, nix);
    k_proto<<<NCLS, 256>>>();
    k_out<<<NSEL/8, 256>>>(nix, out);
}